// round 3
// baseline (speedup 1.0000x reference)
#include <cuda_runtime.h>
#include <math.h>

#define D 256
#define MAXN 50048  // 50000 rounded up to 128

// Scratch (allocation-free rule: __device__ globals)
__device__ float g_agg[(size_t)MAXN * D];
__device__ float g_h[(size_t)MAXN * D];
__device__ float g_x[(size_t)MAXN * D];

// ---------------------------------------------------------------------------
// agg = src (vectorized copy; folds the residual: scatter then adds A@x on top)
// ---------------------------------------------------------------------------
__global__ void copy_f4(const float4* __restrict__ src, float4* __restrict__ dst, int n4) {
    int i = blockIdx.x * blockDim.x + threadIdx.x;
    int stride = gridDim.x * blockDim.x;
    for (; i < n4; i += stride) dst[i] = src[i];
}

// ---------------------------------------------------------------------------
// Edge scatter: agg[dst] += w * x[src], 64 threads per edge, v4 reductions
// ---------------------------------------------------------------------------
__global__ void scatter_edges(const float* __restrict__ x, const int* __restrict__ srcI,
                              const int* __restrict__ dstI, const float* __restrict__ ew,
                              float* __restrict__ agg, int nE) {
    int e = blockIdx.x * blockDim.y + threadIdx.y;
    if (e >= nE) return;
    int s = srcI[e];
    int d = dstI[e];
    float w = ew[e];
    int c = threadIdx.x;  // 0..63 : float4 chunk within the 256-wide row
    float4 v = ((const float4*)(x + (size_t)s * D))[c];
    float* out = agg + (size_t)d * D + c * 4;
    asm volatile("red.global.add.v4.f32 [%0], {%1, %2, %3, %4};"
                 :: "l"(out), "f"(v.x * w), "f"(v.y * w), "f"(v.z * w), "f"(v.w * w)
                 : "memory");
}

// ---------------------------------------------------------------------------
// SGEMM: C[M,256] = A[M,256] @ B[256,256] + bias    (BM=128, BN=128, BK=8, 8x8)
// ---------------------------------------------------------------------------
__global__ __launch_bounds__(256) void sgemm_bias(const float* __restrict__ A,
                                                  const float* __restrict__ B,
                                                  const float* __restrict__ bias,
                                                  float* __restrict__ C, int M) {
    __shared__ float As[8][128];  // transposed A tile: As[k][m]
    __shared__ float Bs[8][128];

    int tid = threadIdx.x;
    int row0 = blockIdx.x * 128;
    int col0 = blockIdx.y * 128;
    int tx = tid & 15;       // 0..15 -> 8 cols each
    int ty = tid >> 4;       // 0..15 -> 8 rows each

    // A-tile load map: 128 rows x 8 k = 256 float4, one per thread
    int arow = tid >> 1;          // 0..127
    int acol4 = (tid & 1) * 4;    // 0 or 4
    bool aval = (row0 + arow) < M;
    const float* Aptr = A + (size_t)(row0 + arow) * D + acol4;

    // B-tile load map: 8 k-rows x 128 cols = 256 float4
    int brow = tid >> 5;          // 0..7
    int bcol4 = (tid & 31) * 4;   // 0,4,...,124
    const float* Bptr = B + (size_t)brow * D + col0 + bcol4;

    float acc[8][8];
#pragma unroll
    for (int i = 0; i < 8; i++)
#pragma unroll
        for (int j = 0; j < 8; j++) acc[i][j] = 0.0f;

    for (int k0 = 0; k0 < D; k0 += 8) {
        float4 a = aval ? *(const float4*)(Aptr + k0) : make_float4(0.f, 0.f, 0.f, 0.f);
        float4 b = *(const float4*)(Bptr + (size_t)k0 * D);
        __syncthreads();
        As[acol4 + 0][arow] = a.x;
        As[acol4 + 1][arow] = a.y;
        As[acol4 + 2][arow] = a.z;
        As[acol4 + 3][arow] = a.w;
        *(float4*)&Bs[brow][bcol4] = b;
        __syncthreads();
#pragma unroll
        for (int kk = 0; kk < 8; kk++) {
            float af[8], bf[8];
            *(float4*)&af[0] = *(const float4*)&As[kk][ty * 8];
            *(float4*)&af[4] = *(const float4*)&As[kk][ty * 8 + 4];
            *(float4*)&bf[0] = *(const float4*)&Bs[kk][tx * 8];
            *(float4*)&bf[4] = *(const float4*)&Bs[kk][tx * 8 + 4];
#pragma unroll
            for (int i = 0; i < 8; i++)
#pragma unroll
                for (int j = 0; j < 8; j++) acc[i][j] += af[i] * bf[j];
        }
    }

    float bv[8];
    *(float4*)&bv[0] = *(const float4*)(bias + col0 + tx * 8);
    *(float4*)&bv[4] = *(const float4*)(bias + col0 + tx * 8 + 4);

#pragma unroll
    for (int i = 0; i < 8; i++) {
        int r = row0 + ty * 8 + i;
        if (r < M) {
            float* cp = C + (size_t)r * D + col0 + tx * 8;
            float4 o0 = make_float4(acc[i][0] + bv[0], acc[i][1] + bv[1],
                                    acc[i][2] + bv[2], acc[i][3] + bv[3]);
            float4 o1 = make_float4(acc[i][4] + bv[4], acc[i][5] + bv[5],
                                    acc[i][6] + bv[6], acc[i][7] + bv[7]);
            *(float4*)cp = o0;
            *(float4*)(cp + 4) = o1;
        }
    }
}

// ---------------------------------------------------------------------------
// LayerNorm (two-pass, matches jnp mean/var) + exact GELU. One warp per row.
// ---------------------------------------------------------------------------
__global__ void ln_gelu(const float* __restrict__ h, const float* __restrict__ gamma,
                        const float* __restrict__ beta, float* __restrict__ out, int M) {
    int row = blockIdx.x * blockDim.y + threadIdx.y;
    if (row >= M) return;
    int lane = threadIdx.x;  // 0..31

    const float4* hp = (const float4*)(h + (size_t)row * D);
    float4 v0 = hp[lane];
    float4 v1 = hp[lane + 32];

    float s = v0.x + v0.y + v0.z + v0.w + v1.x + v1.y + v1.z + v1.w;
#pragma unroll
    for (int o = 16; o > 0; o >>= 1) s += __shfl_xor_sync(0xFFFFFFFFu, s, o);
    float mu = s * (1.0f / D);

    float d0x = v0.x - mu, d0y = v0.y - mu, d0z = v0.z - mu, d0w = v0.w - mu;
    float d1x = v1.x - mu, d1y = v1.y - mu, d1z = v1.z - mu, d1w = v1.w - mu;
    float sq = d0x * d0x + d0y * d0y + d0z * d0z + d0w * d0w +
               d1x * d1x + d1y * d1y + d1z * d1z + d1w * d1w;
#pragma unroll
    for (int o = 16; o > 0; o >>= 1) sq += __shfl_xor_sync(0xFFFFFFFFu, sq, o);
    float rs = rsqrtf(sq * (1.0f / D) + 1e-5f);

    float4 gg0 = ((const float4*)gamma)[lane];
    float4 gg1 = ((const float4*)gamma)[lane + 32];
    float4 bb0 = ((const float4*)beta)[lane];
    float4 bb1 = ((const float4*)beta)[lane + 32];

    const float kInvSqrt2 = 0.70710678118654752f;
    float4 o0, o1;
    {
        float t;
        t = d0x * rs * gg0.x + bb0.x; o0.x = 0.5f * t * (1.0f + erff(t * kInvSqrt2));
        t = d0y * rs * gg0.y + bb0.y; o0.y = 0.5f * t * (1.0f + erff(t * kInvSqrt2));
        t = d0z * rs * gg0.z + bb0.z; o0.z = 0.5f * t * (1.0f + erff(t * kInvSqrt2));
        t = d0w * rs * gg0.w + bb0.w; o0.w = 0.5f * t * (1.0f + erff(t * kInvSqrt2));
        t = d1x * rs * gg1.x + bb1.x; o1.x = 0.5f * t * (1.0f + erff(t * kInvSqrt2));
        t = d1y * rs * gg1.y + bb1.y; o1.y = 0.5f * t * (1.0f + erff(t * kInvSqrt2));
        t = d1z * rs * gg1.z + bb1.z; o1.z = 0.5f * t * (1.0f + erff(t * kInvSqrt2));
        t = d1w * rs * gg1.w + bb1.w; o1.w = 0.5f * t * (1.0f + erff(t * kInvSqrt2));
    }
    float4* op = (float4*)(out + (size_t)row * D);
    op[lane] = o0;
    op[lane + 32] = o1;
}

// ---------------------------------------------------------------------------
// Launch: x = input; for 2 layers: agg=x; scatter; h=agg@W+b; x=gelu(LN(h)).
// Then d_out = x @ Wp + bp.
// ---------------------------------------------------------------------------
extern "C" void kernel_launch(void* const* d_in, const int* in_sizes, int n_in,
                              void* d_out, int out_size) {
    const float* xin = (const float*)d_in[0];
    const int* srcI  = (const int*)d_in[1];
    const int* dstI  = (const int*)d_in[2];
    const float* ew  = (const float*)d_in[3];
    const float* W1  = (const float*)d_in[4];
    const float* b1  = (const float*)d_in[5];
    const float* g1  = (const float*)d_in[6];
    const float* be1 = (const float*)d_in[7];
    const float* W2  = (const float*)d_in[8];
    const float* b2  = (const float*)d_in[9];
    const float* g2  = (const float*)d_in[10];
    const float* be2 = (const float*)d_in[11];
    const float* Wp  = (const float*)d_in[12];
    const float* bp  = (const float*)d_in[13];

    int n  = in_sizes[0] / D;   // 50000
    int nE = in_sizes[1];       // 800000

    float *agg, *hb, *xb;
    cudaGetSymbolAddress((void**)&agg, g_agg);
    cudaGetSymbolAddress((void**)&hb, g_h);
    cudaGetSymbolAddress((void**)&xb, g_x);

    int n4 = n * (D / 4);
    dim3 cpGrid(2048), cpBlk(256);
    dim3 scBlk(64, 4), scGrid((nE + 3) / 4);
    dim3 gmGrid((n + 127) / 128, 2), gmBlk(256);
    dim3 lnBlk(32, 8), lnGrid((n + 7) / 8);

    // ----- Layer 1 -----
    copy_f4<<<cpGrid, cpBlk>>>((const float4*)xin, (float4*)agg, n4);
    scatter_edges<<<scGrid, scBlk>>>(xin, srcI, dstI, ew, agg, nE);
    sgemm_bias<<<gmGrid, gmBlk>>>(agg, W1, b1, hb, n);
    ln_gelu<<<lnGrid, lnBlk>>>(hb, g1, be1, xb, n);

    // ----- Layer 2 -----
    copy_f4<<<cpGrid, cpBlk>>>((const float4*)xb, (float4*)agg, n4);
    scatter_edges<<<scGrid, scBlk>>>(xb, srcI, dstI, ew, agg, nE);
    sgemm_bias<<<gmGrid, gmBlk>>>(agg, W2, b2, hb, n);
    ln_gelu<<<lnGrid, lnBlk>>>(hb, g2, be2, xb, n);

    // ----- Output projection -----
    sgemm_bias<<<gmGrid, gmBlk>>>(xb, Wp, bp, (float*)d_out, n);
}

// round 4
// speedup vs baseline: 1.5086x; 1.5086x over previous
#include <cuda_runtime.h>
#include <math.h>

#define D 256
#define MAXN 50048  // 50000 rounded up to 128

// Scratch (allocation-free rule: __device__ globals)
__device__ float g_agg[(size_t)MAXN * D];
__device__ float g_h[(size_t)MAXN * D];
__device__ float g_x[(size_t)MAXN * D];

// ---------------------------------------------------------------------------
// agg = src (vectorized copy; folds the residual: scatter then adds A@x on top)
// ---------------------------------------------------------------------------
__global__ void copy_f4(const float4* __restrict__ src, float4* __restrict__ dst, int n4) {
    int i = blockIdx.x * blockDim.x + threadIdx.x;
    int stride = gridDim.x * blockDim.x;
    for (; i < n4; i += stride) dst[i] = src[i];
}

// ---------------------------------------------------------------------------
// Edge scatter: agg[dst] += w * x[src], 64 threads per edge, v4 reductions
// ---------------------------------------------------------------------------
__global__ void scatter_edges(const float* __restrict__ x, const int* __restrict__ srcI,
                              const int* __restrict__ dstI, const float* __restrict__ ew,
                              float* __restrict__ agg, int nE) {
    int e = blockIdx.x * blockDim.y + threadIdx.y;
    if (e >= nE) return;
    int s = srcI[e];
    int d = dstI[e];
    float w = ew[e];
    int c = threadIdx.x;  // 0..63 : float4 chunk within the 256-wide row
    float4 v = ((const float4*)(x + (size_t)s * D))[c];
    float* out = agg + (size_t)d * D + c * 4;
    asm volatile("red.global.add.v4.f32 [%0], {%1, %2, %3, %4};"
                 :: "l"(out), "f"(v.x * w), "f"(v.y * w), "f"(v.z * w), "f"(v.w * w)
                 : "memory");
}

// ---------------------------------------------------------------------------
// TF32 tensor-core GEMM: C[M,256] = A[M,256] @ B[256,256] + bias
// BM=128, BN=128, BK=32; 8 warps (4Mx2N), warp tile 32x64 via m16n8k8 mma.
// ---------------------------------------------------------------------------
__device__ __forceinline__ unsigned f2tf(float f) {
    unsigned r;
    asm("cvt.rna.tf32.f32 %0, %1;" : "=r"(r) : "f"(f));
    return r;
}

__device__ __forceinline__ void mma_tf32(float& d0, float& d1, float& d2, float& d3,
                                         unsigned a0, unsigned a1, unsigned a2, unsigned a3,
                                         unsigned b0, unsigned b1) {
    asm volatile(
        "mma.sync.aligned.m16n8k8.row.col.f32.tf32.tf32.f32 "
        "{%0,%1,%2,%3}, {%4,%5,%6,%7}, {%8,%9}, {%0,%1,%2,%3};"
        : "+f"(d0), "+f"(d1), "+f"(d2), "+f"(d3)
        : "r"(a0), "r"(a1), "r"(a2), "r"(a3), "r"(b0), "r"(b1));
}

#define AS_STRIDE 36   // 128 rows; bank = (4g + tig) -> conflict-free A frag loads
#define BS_STRIDE 136  // 32 k-rows; bank = (8k' + g) -> conflict-free B frag loads

__global__ __launch_bounds__(256) void gemm_tf32(const float* __restrict__ A,
                                                 const float* __restrict__ B,
                                                 const float* __restrict__ bias,
                                                 float* __restrict__ C, int M) {
    __shared__ float As[128 * AS_STRIDE];
    __shared__ float Bs[32 * BS_STRIDE];

    int tid = threadIdx.x;
    int row0 = blockIdx.x * 128;
    int col0 = blockIdx.y * 128;

    int wid = tid >> 5;
    int lane = tid & 31;
    int warpM = wid & 3;   // 4 warps down M (32 rows each)
    int warpN = wid >> 2;  // 2 warps across N (64 cols each)
    int g = lane >> 2;     // groupID 0..7
    int tig = lane & 3;    // thread-in-group 0..3

    // A global->smem map: thread loads 16 contiguous floats of one row
    int aRow = tid >> 1;           // 0..127
    int aK = (tid & 1) * 16;       // 0 or 16
    bool aValid = (row0 + aRow) < M;
    const float* Ag = A + (size_t)(row0 + aRow) * D + aK;

    // B global->smem map: thread loads one float4 from each of 4 k-rows
    int bF4 = (tid & 31) * 4;      // col offset 0..124
    int bK = tid >> 5;             // base k-row 0..7
    const float* Bg = B + (size_t)bK * D + col0 + bF4;

    float acc[2][8][4];
#pragma unroll
    for (int mt = 0; mt < 2; mt++)
#pragma unroll
        for (int nt = 0; nt < 8; nt++)
#pragma unroll
            for (int c = 0; c < 4; c++) acc[mt][nt][c] = 0.0f;

    for (int k0 = 0; k0 < D; k0 += 32) {
        // --- global loads to registers ---
        float4 av[4];
#pragma unroll
        for (int j = 0; j < 4; j++)
            av[j] = aValid ? *(const float4*)(Ag + k0 + j * 4)
                           : make_float4(0.f, 0.f, 0.f, 0.f);
        float4 bv4[4];
#pragma unroll
        for (int r = 0; r < 4; r++)
            bv4[r] = *(const float4*)(Bg + (size_t)(k0 + r * 8) * D);

        __syncthreads();  // previous tile fully consumed

        // --- smem stores (tf32-rounded) ---
        float* asp = &As[aRow * AS_STRIDE + aK];
#pragma unroll
        for (int j = 0; j < 4; j++) {
            asp[j * 4 + 0] = __uint_as_float(f2tf(av[j].x));
            asp[j * 4 + 1] = __uint_as_float(f2tf(av[j].y));
            asp[j * 4 + 2] = __uint_as_float(f2tf(av[j].z));
            asp[j * 4 + 3] = __uint_as_float(f2tf(av[j].w));
        }
#pragma unroll
        for (int r = 0; r < 4; r++) {
            float4 t;
            t.x = __uint_as_float(f2tf(bv4[r].x));
            t.y = __uint_as_float(f2tf(bv4[r].y));
            t.z = __uint_as_float(f2tf(bv4[r].z));
            t.w = __uint_as_float(f2tf(bv4[r].w));
            *(float4*)&Bs[(bK + r * 8) * BS_STRIDE + bF4] = t;
        }
        __syncthreads();

        // --- compute: 4 x k8 steps ---
#pragma unroll
        for (int ks = 0; ks < 4; ks++) {
            int kk = ks * 8;
            unsigned af[2][4];
#pragma unroll
            for (int mt = 0; mt < 2; mt++) {
                int r = warpM * 32 + mt * 16 + g;
                const float* ap = &As[r * AS_STRIDE + kk];
                af[mt][0] = __float_as_uint(ap[tig]);
                af[mt][1] = __float_as_uint(ap[8 * AS_STRIDE + tig]);
                af[mt][2] = __float_as_uint(ap[tig + 4]);
                af[mt][3] = __float_as_uint(ap[8 * AS_STRIDE + tig + 4]);
            }
            unsigned bf[8][2];
#pragma unroll
            for (int nt = 0; nt < 8; nt++) {
                int c = warpN * 64 + nt * 8 + g;
                bf[nt][0] = __float_as_uint(Bs[(kk + tig) * BS_STRIDE + c]);
                bf[nt][1] = __float_as_uint(Bs[(kk + tig + 4) * BS_STRIDE + c]);
            }
#pragma unroll
            for (int mt = 0; mt < 2; mt++)
#pragma unroll
                for (int nt = 0; nt < 8; nt++)
                    mma_tf32(acc[mt][nt][0], acc[mt][nt][1], acc[mt][nt][2], acc[mt][nt][3],
                             af[mt][0], af[mt][1], af[mt][2], af[mt][3],
                             bf[nt][0], bf[nt][1]);
        }
    }

    // --- epilogue: bias add + store ---
#pragma unroll
    for (int mt = 0; mt < 2; mt++) {
#pragma unroll
        for (int nt = 0; nt < 8; nt++) {
            int col = col0 + warpN * 64 + nt * 8 + 2 * tig;
            float2 bb = *(const float2*)(bias + col);
            int r0 = row0 + warpM * 32 + mt * 16 + g;
            if (r0 < M) {
                float2 o = make_float2(acc[mt][nt][0] + bb.x, acc[mt][nt][1] + bb.y);
                *(float2*)(C + (size_t)r0 * D + col) = o;
            }
            int r1 = r0 + 8;
            if (r1 < M) {
                float2 o = make_float2(acc[mt][nt][2] + bb.x, acc[mt][nt][3] + bb.y);
                *(float2*)(C + (size_t)r1 * D + col) = o;
            }
        }
    }
}

// ---------------------------------------------------------------------------
// LayerNorm (two-pass, matches jnp mean/var) + exact GELU. One warp per row.
// ---------------------------------------------------------------------------
__global__ void ln_gelu(const float* __restrict__ h, const float* __restrict__ gamma,
                        const float* __restrict__ beta, float* __restrict__ out, int M) {
    int row = blockIdx.x * blockDim.y + threadIdx.y;
    if (row >= M) return;
    int lane = threadIdx.x;  // 0..31

    const float4* hp = (const float4*)(h + (size_t)row * D);
    float4 v0 = hp[lane];
    float4 v1 = hp[lane + 32];

    float s = v0.x + v0.y + v0.z + v0.w + v1.x + v1.y + v1.z + v1.w;
#pragma unroll
    for (int o = 16; o > 0; o >>= 1) s += __shfl_xor_sync(0xFFFFFFFFu, s, o);
    float mu = s * (1.0f / D);

    float d0x = v0.x - mu, d0y = v0.y - mu, d0z = v0.z - mu, d0w = v0.w - mu;
    float d1x = v1.x - mu, d1y = v1.y - mu, d1z = v1.z - mu, d1w = v1.w - mu;
    float sq = d0x * d0x + d0y * d0y + d0z * d0z + d0w * d0w +
               d1x * d1x + d1y * d1y + d1z * d1z + d1w * d1w;
#pragma unroll
    for (int o = 16; o > 0; o >>= 1) sq += __shfl_xor_sync(0xFFFFFFFFu, sq, o);
    float rs = rsqrtf(sq * (1.0f / D) + 1e-5f);

    float4 gg0 = ((const float4*)gamma)[lane];
    float4 gg1 = ((const float4*)gamma)[lane + 32];
    float4 bb0 = ((const float4*)beta)[lane];
    float4 bb1 = ((const float4*)beta)[lane + 32];

    const float kInvSqrt2 = 0.70710678118654752f;
    float4 o0, o1;
    {
        float t;
        t = d0x * rs * gg0.x + bb0.x; o0.x = 0.5f * t * (1.0f + erff(t * kInvSqrt2));
        t = d0y * rs * gg0.y + bb0.y; o0.y = 0.5f * t * (1.0f + erff(t * kInvSqrt2));
        t = d0z * rs * gg0.z + bb0.z; o0.z = 0.5f * t * (1.0f + erff(t * kInvSqrt2));
        t = d0w * rs * gg0.w + bb0.w; o0.w = 0.5f * t * (1.0f + erff(t * kInvSqrt2));
        t = d1x * rs * gg1.x + bb1.x; o1.x = 0.5f * t * (1.0f + erff(t * kInvSqrt2));
        t = d1y * rs * gg1.y + bb1.y; o1.y = 0.5f * t * (1.0f + erff(t * kInvSqrt2));
        t = d1z * rs * gg1.z + bb1.z; o1.z = 0.5f * t * (1.0f + erff(t * kInvSqrt2));
        t = d1w * rs * gg1.w + bb1.w; o1.w = 0.5f * t * (1.0f + erff(t * kInvSqrt2));
    }
    float4* op = (float4*)(out + (size_t)row * D);
    op[lane] = o0;
    op[lane + 32] = o1;
}

// ---------------------------------------------------------------------------
// Launch: x = input; for 2 layers: agg=x; scatter; h=agg@W+b; x=gelu(LN(h)).
// Then d_out = x @ Wp + bp.
// ---------------------------------------------------------------------------
extern "C" void kernel_launch(void* const* d_in, const int* in_sizes, int n_in,
                              void* d_out, int out_size) {
    const float* xin = (const float*)d_in[0];
    const int* srcI  = (const int*)d_in[1];
    const int* dstI  = (const int*)d_in[2];
    const float* ew  = (const float*)d_in[3];
    const float* W1  = (const float*)d_in[4];
    const float* b1  = (const float*)d_in[5];
    const float* g1  = (const float*)d_in[6];
    const float* be1 = (const float*)d_in[7];
    const float* W2  = (const float*)d_in[8];
    const float* b2  = (const float*)d_in[9];
    const float* g2  = (const float*)d_in[10];
    const float* be2 = (const float*)d_in[11];
    const float* Wp  = (const float*)d_in[12];
    const float* bp  = (const float*)d_in[13];

    int n  = in_sizes[0] / D;   // 50000
    int nE = in_sizes[1];       // 800000

    float *agg, *hb, *xb;
    cudaGetSymbolAddress((void**)&agg, g_agg);
    cudaGetSymbolAddress((void**)&hb, g_h);
    cudaGetSymbolAddress((void**)&xb, g_x);

    int n4 = n * (D / 4);
    dim3 cpGrid(2048), cpBlk(256);
    dim3 scBlk(64, 4), scGrid((nE + 3) / 4);
    dim3 gmGrid((n + 127) / 128, 2), gmBlk(256);
    dim3 lnBlk(32, 8), lnGrid((n + 7) / 8);

    // ----- Layer 1 -----
    copy_f4<<<cpGrid, cpBlk>>>((const float4*)xin, (float4*)agg, n4);
    scatter_edges<<<scGrid, scBlk>>>(xin, srcI, dstI, ew, agg, nE);
    gemm_tf32<<<gmGrid, gmBlk>>>(agg, W1, b1, hb, n);
    ln_gelu<<<lnGrid, lnBlk>>>(hb, g1, be1, xb, n);

    // ----- Layer 2 -----
    copy_f4<<<cpGrid, cpBlk>>>((const float4*)xb, (float4*)agg, n4);
    scatter_edges<<<scGrid, scBlk>>>(xb, srcI, dstI, ew, agg, nE);
    gemm_tf32<<<gmGrid, gmBlk>>>(agg, W2, b2, hb, n);
    ln_gelu<<<lnGrid, lnBlk>>>(hb, g2, be2, xb, n);

    // ----- Output projection -----
    gemm_tf32<<<gmGrid, gmBlk>>>(xb, Wp, bp, (float*)d_out, n);
}

// round 5
// speedup vs baseline: 2.1604x; 1.4320x over previous
#include <cuda_runtime.h>
#include <math.h>

#define D 256
#define MAXN 50048   // 50000 rounded up to 128
#define MAXE 1048576 // >= 800000

// Scratch (allocation-free rule: __device__ globals)
__device__ float g_agg[(size_t)MAXN * D];
__device__ float g_h[(size_t)MAXN * D];
__device__ float g_x[(size_t)MAXN * D];
__device__ int   g_deg[MAXN + 1];
__device__ int   g_rowptr[MAXN + 1];
__device__ int   g_wptr[MAXN + 1];
__device__ int   g_esrc[MAXE];
__device__ float g_ew[MAXE];

// ---------------------------------------------------------------------------
// CSR build: zero -> histogram -> scan -> fill
// ---------------------------------------------------------------------------
__global__ void zero_int(int* p, int n) {
    int i = blockIdx.x * blockDim.x + threadIdx.x;
    if (i < n) p[i] = 0;
}

__global__ void hist_deg(const int* __restrict__ dstI, int* __restrict__ deg, int nE) {
    int i = blockIdx.x * blockDim.x + threadIdx.x;
    int stride = gridDim.x * blockDim.x;
    for (; i < nE; i += stride) atomicAdd(&deg[dstI[i]], 1);
}

#define SCAN_T 1024
__global__ __launch_bounds__(SCAN_T) void scan_deg(const int* __restrict__ deg,
                                                   int* __restrict__ rowptr,
                                                   int* __restrict__ wptr, int n) {
    __shared__ int sums[SCAN_T];
    int t = threadIdx.x;
    int chunk = (n + SCAN_T - 1) / SCAN_T;
    int beg = t * chunk;
    int end = min(beg + chunk, n);
    int s = 0;
    for (int i = beg; i < end; i++) s += deg[i];
    sums[t] = s;
    __syncthreads();
    // Hillis-Steele inclusive scan
    for (int o = 1; o < SCAN_T; o <<= 1) {
        int v = (t >= o) ? sums[t - o] : 0;
        __syncthreads();
        sums[t] += v;
        __syncthreads();
    }
    int base = (t == 0) ? 0 : sums[t - 1];
    for (int i = beg; i < end; i++) {
        rowptr[i] = base;
        wptr[i] = base;
        base += deg[i];
    }
    if (t == 0) rowptr[n] = sums[SCAN_T - 1];
}

__global__ void fill_csr(const int* __restrict__ srcI, const int* __restrict__ dstI,
                         const float* __restrict__ ew, int* __restrict__ wptr,
                         int* __restrict__ esrc, float* __restrict__ ewOut, int nE) {
    int i = blockIdx.x * blockDim.x + threadIdx.x;
    int stride = gridDim.x * blockDim.x;
    for (; i < nE; i += stride) {
        int pos = atomicAdd(&wptr[dstI[i]], 1);
        esrc[pos] = srcI[i];
        ewOut[pos] = ew[i];
    }
}

// ---------------------------------------------------------------------------
// Gather: agg[i] = x[i] + sum_e w_e * x[src_e]. One warp per node, no atomics.
// ---------------------------------------------------------------------------
__device__ __forceinline__ void fma4(float4& a, float w, const float4& v) {
    a.x = fmaf(w, v.x, a.x);
    a.y = fmaf(w, v.y, a.y);
    a.z = fmaf(w, v.z, a.z);
    a.w = fmaf(w, v.w, a.w);
}

__global__ __launch_bounds__(256) void gather_agg(const float* __restrict__ x,
                                                  const int* __restrict__ rowptr,
                                                  const int* __restrict__ esrc,
                                                  const float* __restrict__ ew,
                                                  float* __restrict__ agg, int n) {
    int warp = (blockIdx.x * blockDim.x + threadIdx.x) >> 5;
    if (warp >= n) return;
    int lane = threadIdx.x & 31;

    const float4* xr = (const float4*)(x + (size_t)warp * D);
    float4 a0 = xr[lane];
    float4 a1 = xr[lane + 32];

    int e = rowptr[warp];
    int end = rowptr[warp + 1];
    for (; e + 2 <= end; e += 2) {
        int s0 = esrc[e], s1 = esrc[e + 1];
        float w0 = ew[e], w1 = ew[e + 1];
        const float4* p0 = (const float4*)(x + (size_t)s0 * D);
        const float4* p1 = (const float4*)(x + (size_t)s1 * D);
        float4 v00 = p0[lane], v01 = p0[lane + 32];
        float4 v10 = p1[lane], v11 = p1[lane + 32];
        fma4(a0, w0, v00);
        fma4(a1, w0, v01);
        fma4(a0, w1, v10);
        fma4(a1, w1, v11);
    }
    if (e < end) {
        int s0 = esrc[e];
        float w0 = ew[e];
        const float4* p0 = (const float4*)(x + (size_t)s0 * D);
        fma4(a0, w0, p0[lane]);
        fma4(a1, w0, p0[lane + 32]);
    }

    float4* ar = (float4*)(agg + (size_t)warp * D);
    ar[lane] = a0;
    ar[lane + 32] = a1;
}

// ---------------------------------------------------------------------------
// TF32 tensor-core GEMM: C[M,256] = A[M,256] @ B[256,256] + bias
// BM=128, BN=128, BK=32; 8 warps (4Mx2N), warp tile 32x64 via m16n8k8 mma.
// ---------------------------------------------------------------------------
__device__ __forceinline__ unsigned f2tf(float f) {
    unsigned r;
    asm("cvt.rna.tf32.f32 %0, %1;" : "=r"(r) : "f"(f));
    return r;
}

__device__ __forceinline__ void mma_tf32(float& d0, float& d1, float& d2, float& d3,
                                         unsigned a0, unsigned a1, unsigned a2, unsigned a3,
                                         unsigned b0, unsigned b1) {
    asm volatile(
        "mma.sync.aligned.m16n8k8.row.col.f32.tf32.tf32.f32 "
        "{%0,%1,%2,%3}, {%4,%5,%6,%7}, {%8,%9}, {%0,%1,%2,%3};"
        : "+f"(d0), "+f"(d1), "+f"(d2), "+f"(d3)
        : "r"(a0), "r"(a1), "r"(a2), "r"(a3), "r"(b0), "r"(b1));
}

#define AS_STRIDE 36   // conflict-free A frag loads
#define BS_STRIDE 136  // conflict-free B frag loads

__global__ __launch_bounds__(256) void gemm_tf32(const float* __restrict__ A,
                                                 const float* __restrict__ B,
                                                 const float* __restrict__ bias,
                                                 float* __restrict__ C, int M) {
    __shared__ float As[128 * AS_STRIDE];
    __shared__ float Bs[32 * BS_STRIDE];

    int tid = threadIdx.x;
    int row0 = blockIdx.x * 128;
    int col0 = blockIdx.y * 128;

    int wid = tid >> 5;
    int lane = tid & 31;
    int warpM = wid & 3;
    int warpN = wid >> 2;
    int g = lane >> 2;
    int tig = lane & 3;

    int aRow = tid >> 1;
    int aK = (tid & 1) * 16;
    bool aValid = (row0 + aRow) < M;
    const float* Ag = A + (size_t)(row0 + aRow) * D + aK;

    int bF4 = (tid & 31) * 4;
    int bK = tid >> 5;
    const float* Bg = B + (size_t)bK * D + col0 + bF4;

    float acc[2][8][4];
#pragma unroll
    for (int mt = 0; mt < 2; mt++)
#pragma unroll
        for (int nt = 0; nt < 8; nt++)
#pragma unroll
            for (int c = 0; c < 4; c++) acc[mt][nt][c] = 0.0f;

    for (int k0 = 0; k0 < D; k0 += 32) {
        float4 av[4];
#pragma unroll
        for (int j = 0; j < 4; j++)
            av[j] = aValid ? *(const float4*)(Ag + k0 + j * 4)
                           : make_float4(0.f, 0.f, 0.f, 0.f);
        float4 bv4[4];
#pragma unroll
        for (int r = 0; r < 4; r++)
            bv4[r] = *(const float4*)(Bg + (size_t)(k0 + r * 8) * D);

        __syncthreads();

        float* asp = &As[aRow * AS_STRIDE + aK];
#pragma unroll
        for (int j = 0; j < 4; j++) {
            asp[j * 4 + 0] = __uint_as_float(f2tf(av[j].x));
            asp[j * 4 + 1] = __uint_as_float(f2tf(av[j].y));
            asp[j * 4 + 2] = __uint_as_float(f2tf(av[j].z));
            asp[j * 4 + 3] = __uint_as_float(f2tf(av[j].w));
        }
#pragma unroll
        for (int r = 0; r < 4; r++) {
            float4 t;
            t.x = __uint_as_float(f2tf(bv4[r].x));
            t.y = __uint_as_float(f2tf(bv4[r].y));
            t.z = __uint_as_float(f2tf(bv4[r].z));
            t.w = __uint_as_float(f2tf(bv4[r].w));
            *(float4*)&Bs[(bK + r * 8) * BS_STRIDE + bF4] = t;
        }
        __syncthreads();

#pragma unroll
        for (int ks = 0; ks < 4; ks++) {
            int kk = ks * 8;
            unsigned af[2][4];
#pragma unroll
            for (int mt = 0; mt < 2; mt++) {
                int r = warpM * 32 + mt * 16 + g;
                const float* ap = &As[r * AS_STRIDE + kk];
                af[mt][0] = __float_as_uint(ap[tig]);
                af[mt][1] = __float_as_uint(ap[8 * AS_STRIDE + tig]);
                af[mt][2] = __float_as_uint(ap[tig + 4]);
                af[mt][3] = __float_as_uint(ap[8 * AS_STRIDE + tig + 4]);
            }
            unsigned bf[8][2];
#pragma unroll
            for (int nt = 0; nt < 8; nt++) {
                int c = warpN * 64 + nt * 8 + g;
                bf[nt][0] = __float_as_uint(Bs[(kk + tig) * BS_STRIDE + c]);
                bf[nt][1] = __float_as_uint(Bs[(kk + tig + 4) * BS_STRIDE + c]);
            }
#pragma unroll
            for (int mt = 0; mt < 2; mt++)
#pragma unroll
                for (int nt = 0; nt < 8; nt++)
                    mma_tf32(acc[mt][nt][0], acc[mt][nt][1], acc[mt][nt][2], acc[mt][nt][3],
                             af[mt][0], af[mt][1], af[mt][2], af[mt][3],
                             bf[nt][0], bf[nt][1]);
        }
    }

#pragma unroll
    for (int mt = 0; mt < 2; mt++) {
#pragma unroll
        for (int nt = 0; nt < 8; nt++) {
            int col = col0 + warpN * 64 + nt * 8 + 2 * tig;
            float2 bb = *(const float2*)(bias + col);
            int r0 = row0 + warpM * 32 + mt * 16 + g;
            if (r0 < M) {
                float2 o = make_float2(acc[mt][nt][0] + bb.x, acc[mt][nt][1] + bb.y);
                *(float2*)(C + (size_t)r0 * D + col) = o;
            }
            int r1 = r0 + 8;
            if (r1 < M) {
                float2 o = make_float2(acc[mt][nt][2] + bb.x, acc[mt][nt][3] + bb.y);
                *(float2*)(C + (size_t)r1 * D + col) = o;
            }
        }
    }
}

// ---------------------------------------------------------------------------
// LayerNorm (two-pass, matches jnp mean/var) + exact GELU. One warp per row.
// ---------------------------------------------------------------------------
__global__ void ln_gelu(const float* __restrict__ h, const float* __restrict__ gamma,
                        const float* __restrict__ beta, float* __restrict__ out, int M) {
    int row = blockIdx.x * blockDim.y + threadIdx.y;
    if (row >= M) return;
    int lane = threadIdx.x;

    const float4* hp = (const float4*)(h + (size_t)row * D);
    float4 v0 = hp[lane];
    float4 v1 = hp[lane + 32];

    float s = v0.x + v0.y + v0.z + v0.w + v1.x + v1.y + v1.z + v1.w;
#pragma unroll
    for (int o = 16; o > 0; o >>= 1) s += __shfl_xor_sync(0xFFFFFFFFu, s, o);
    float mu = s * (1.0f / D);

    float d0x = v0.x - mu, d0y = v0.y - mu, d0z = v0.z - mu, d0w = v0.w - mu;
    float d1x = v1.x - mu, d1y = v1.y - mu, d1z = v1.z - mu, d1w = v1.w - mu;
    float sq = d0x * d0x + d0y * d0y + d0z * d0z + d0w * d0w +
               d1x * d1x + d1y * d1y + d1z * d1z + d1w * d1w;
#pragma unroll
    for (int o = 16; o > 0; o >>= 1) sq += __shfl_xor_sync(0xFFFFFFFFu, sq, o);
    float rs = rsqrtf(sq * (1.0f / D) + 1e-5f);

    float4 gg0 = ((const float4*)gamma)[lane];
    float4 gg1 = ((const float4*)gamma)[lane + 32];
    float4 bb0 = ((const float4*)beta)[lane];
    float4 bb1 = ((const float4*)beta)[lane + 32];

    const float kInvSqrt2 = 0.70710678118654752f;
    float4 o0, o1;
    {
        float t;
        t = d0x * rs * gg0.x + bb0.x; o0.x = 0.5f * t * (1.0f + erff(t * kInvSqrt2));
        t = d0y * rs * gg0.y + bb0.y; o0.y = 0.5f * t * (1.0f + erff(t * kInvSqrt2));
        t = d0z * rs * gg0.z + bb0.z; o0.z = 0.5f * t * (1.0f + erff(t * kInvSqrt2));
        t = d0w * rs * gg0.w + bb0.w; o0.w = 0.5f * t * (1.0f + erff(t * kInvSqrt2));
        t = d1x * rs * gg1.x + bb1.x; o1.x = 0.5f * t * (1.0f + erff(t * kInvSqrt2));
        t = d1y * rs * gg1.y + bb1.y; o1.y = 0.5f * t * (1.0f + erff(t * kInvSqrt2));
        t = d1z * rs * gg1.z + bb1.z; o1.z = 0.5f * t * (1.0f + erff(t * kInvSqrt2));
        t = d1w * rs * gg1.w + bb1.w; o1.w = 0.5f * t * (1.0f + erff(t * kInvSqrt2));
    }
    float4* op = (float4*)(out + (size_t)row * D);
    op[lane] = o0;
    op[lane + 32] = o1;
}

// ---------------------------------------------------------------------------
extern "C" void kernel_launch(void* const* d_in, const int* in_sizes, int n_in,
                              void* d_out, int out_size) {
    const float* xin = (const float*)d_in[0];
    const int* srcI  = (const int*)d_in[1];
    const int* dstI  = (const int*)d_in[2];
    const float* ew  = (const float*)d_in[3];
    const float* W1  = (const float*)d_in[4];
    const float* b1  = (const float*)d_in[5];
    const float* g1  = (const float*)d_in[6];
    const float* be1 = (const float*)d_in[7];
    const float* W2  = (const float*)d_in[8];
    const float* b2  = (const float*)d_in[9];
    const float* g2  = (const float*)d_in[10];
    const float* be2 = (const float*)d_in[11];
    const float* Wp  = (const float*)d_in[12];
    const float* bp  = (const float*)d_in[13];

    int n  = in_sizes[0] / D;   // 50000
    int nE = in_sizes[1];       // 800000

    float *agg, *hb, *xb, *ewc;
    int *deg, *rowptr, *wptr, *esrc;
    cudaGetSymbolAddress((void**)&agg, g_agg);
    cudaGetSymbolAddress((void**)&hb, g_h);
    cudaGetSymbolAddress((void**)&xb, g_x);
    cudaGetSymbolAddress((void**)&deg, g_deg);
    cudaGetSymbolAddress((void**)&rowptr, g_rowptr);
    cudaGetSymbolAddress((void**)&wptr, g_wptr);
    cudaGetSymbolAddress((void**)&esrc, g_esrc);
    cudaGetSymbolAddress((void**)&ewc, g_ew);

    dim3 gmGrid((n + 127) / 128, 2), gmBlk(256);
    dim3 lnBlk(32, 8), lnGrid((n + 7) / 8);
    int gaBlocks = (n + 7) / 8;  // 8 warps per 256-thread block, warp per node

    // ----- CSR build (once per launch; graph static within a call) -----
    zero_int<<<(n + 255) / 256, 256>>>(deg, n);
    hist_deg<<<1024, 256>>>(dstI, deg, nE);
    scan_deg<<<1, SCAN_T>>>(deg, rowptr, wptr, n);
    fill_csr<<<1024, 256>>>(srcI, dstI, ew, wptr, esrc, ewc, nE);

    // ----- Layer 1 -----
    gather_agg<<<gaBlocks, 256>>>(xin, rowptr, esrc, ewc, agg, n);
    gemm_tf32<<<gmGrid, gmBlk>>>(agg, W1, b1, hb, n);
    ln_gelu<<<lnGrid, lnBlk>>>(hb, g1, be1, xb, n);

    // ----- Layer 2 -----
    gather_agg<<<gaBlocks, 256>>>(xb, rowptr, esrc, ewc, agg, n);
    gemm_tf32<<<gmGrid, gmBlk>>>(agg, W2, b2, hb, n);
    ln_gelu<<<lnGrid, lnBlk>>>(hb, g2, be2, xb, n);

    // ----- Output projection -----
    gemm_tf32<<<gmGrid, gmBlk>>>(xb, Wp, bp, (float*)d_out, n);
}

// round 6
// speedup vs baseline: 2.3245x; 1.0760x over previous
#include <cuda_runtime.h>
#include <math.h>

#define D 256
#define MAXN 50048   // 50000 rounded up to 128
#define MAXE 1048576 // >= 800000

// Scratch (allocation-free rule: __device__ globals)
__device__ float g_agg[(size_t)MAXN * D];
__device__ float g_x[(size_t)MAXN * D];
__device__ int   g_deg[MAXN + 1];
__device__ int   g_rowptr[MAXN + 1];
__device__ int   g_wptr[MAXN + 1];
__device__ int   g_esrc[MAXE];
__device__ float g_ew[MAXE];

// ---------------------------------------------------------------------------
// CSR build: zero -> histogram -> scan -> fill
// ---------------------------------------------------------------------------
__global__ void zero_int(int* p, int n) {
    int i = blockIdx.x * blockDim.x + threadIdx.x;
    if (i < n) p[i] = 0;
}

__global__ void hist_deg(const int* __restrict__ dstI, int* __restrict__ deg, int nE) {
    int i = blockIdx.x * blockDim.x + threadIdx.x;
    int stride = gridDim.x * blockDim.x;
    for (; i < nE; i += stride) atomicAdd(&deg[dstI[i]], 1);
}

#define SCAN_T 1024
__global__ __launch_bounds__(SCAN_T) void scan_deg(const int* __restrict__ deg,
                                                   int* __restrict__ rowptr,
                                                   int* __restrict__ wptr, int n) {
    __shared__ int sums[SCAN_T];
    int t = threadIdx.x;
    int chunk = (n + SCAN_T - 1) / SCAN_T;
    int beg = t * chunk;
    int end = min(beg + chunk, n);
    int s = 0;
    for (int i = beg; i < end; i++) s += deg[i];
    sums[t] = s;
    __syncthreads();
    for (int o = 1; o < SCAN_T; o <<= 1) {
        int v = (t >= o) ? sums[t - o] : 0;
        __syncthreads();
        sums[t] += v;
        __syncthreads();
    }
    int base = (t == 0) ? 0 : sums[t - 1];
    for (int i = beg; i < end; i++) {
        rowptr[i] = base;
        wptr[i] = base;
        base += deg[i];
    }
    if (t == 0) rowptr[n] = sums[SCAN_T - 1];
}

__global__ void fill_csr(const int* __restrict__ srcI, const int* __restrict__ dstI,
                         const float* __restrict__ ew, int* __restrict__ wptr,
                         int* __restrict__ esrc, float* __restrict__ ewOut, int nE) {
    int i = blockIdx.x * blockDim.x + threadIdx.x;
    int stride = gridDim.x * blockDim.x;
    for (; i < nE; i += stride) {
        int pos = atomicAdd(&wptr[dstI[i]], 1);
        esrc[pos] = srcI[i];
        ewOut[pos] = ew[i];
    }
}

// ---------------------------------------------------------------------------
// Gather: agg[i] = x[i] + sum_e w_e * x[src_e]. One warp per node, no atomics.
// ---------------------------------------------------------------------------
__device__ __forceinline__ void fma4(float4& a, float w, const float4& v) {
    a.x = fmaf(w, v.x, a.x);
    a.y = fmaf(w, v.y, a.y);
    a.z = fmaf(w, v.z, a.z);
    a.w = fmaf(w, v.w, a.w);
}

__global__ __launch_bounds__(256) void gather_agg(const float* __restrict__ x,
                                                  const int* __restrict__ rowptr,
                                                  const int* __restrict__ esrc,
                                                  const float* __restrict__ ew,
                                                  float* __restrict__ agg, int n) {
    int warp = (blockIdx.x * blockDim.x + threadIdx.x) >> 5;
    if (warp >= n) return;
    int lane = threadIdx.x & 31;

    const float4* xr = (const float4*)(x + (size_t)warp * D);
    float4 a0 = xr[lane];
    float4 a1 = xr[lane + 32];

    int e = rowptr[warp];
    int end = rowptr[warp + 1];
    for (; e + 2 <= end; e += 2) {
        int s0 = esrc[e], s1 = esrc[e + 1];
        float w0 = ew[e], w1 = ew[e + 1];
        const float4* p0 = (const float4*)(x + (size_t)s0 * D);
        const float4* p1 = (const float4*)(x + (size_t)s1 * D);
        float4 v00 = p0[lane], v01 = p0[lane + 32];
        float4 v10 = p1[lane], v11 = p1[lane + 32];
        fma4(a0, w0, v00);
        fma4(a1, w0, v01);
        fma4(a0, w1, v10);
        fma4(a1, w1, v11);
    }
    if (e < end) {
        int s0 = esrc[e];
        float w0 = ew[e];
        const float4* p0 = (const float4*)(x + (size_t)s0 * D);
        fma4(a0, w0, p0[lane]);
        fma4(a1, w0, p0[lane + 32]);
    }

    float4* ar = (float4*)(agg + (size_t)warp * D);
    ar[lane] = a0;
    ar[lane + 32] = a1;
}

// ---------------------------------------------------------------------------
// Fused TF32 GEMM (+bias, optional LayerNorm+GELU epilogue)
// C[M,256] = epilogue(A[M,256] @ B[256,256] + bias)
// BM=64, BN=256 (full width -> per-row LN possible), BK=32.
// 8 warps as 2(M) x 4(N); warp tile 32x64 via m16n8k8 tf32 mma.
// ---------------------------------------------------------------------------
__device__ __forceinline__ unsigned f2tf(float f) {
    unsigned r;
    asm("cvt.rna.tf32.f32 %0, %1;" : "=r"(r) : "f"(f));
    return r;
}

__device__ __forceinline__ void mma_tf32(float& d0, float& d1, float& d2, float& d3,
                                         unsigned a0, unsigned a1, unsigned a2, unsigned a3,
                                         unsigned b0, unsigned b1) {
    asm volatile(
        "mma.sync.aligned.m16n8k8.row.col.f32.tf32.tf32.f32 "
        "{%0,%1,%2,%3}, {%4,%5,%6,%7}, {%8,%9}, {%0,%1,%2,%3};"
        : "+f"(d0), "+f"(d1), "+f"(d2), "+f"(d3)
        : "r"(a0), "r"(a1), "r"(a2), "r"(a3), "r"(b0), "r"(b1));
}

__device__ __forceinline__ float gelu_exact(float t) {
    return 0.5f * t * (1.0f + erff(t * 0.70710678118654752f));
}

#define AS_STRIDE 36   // conflict-free A frag loads (bank = 4g + tig)
#define BS_STRIDE 264  // conflict-free B frag loads (bank = 8k' + g)

template <bool DO_LN>
__global__ __launch_bounds__(256) void gemm_fused(const float* __restrict__ A,
                                                  const float* __restrict__ B,
                                                  const float* __restrict__ bias,
                                                  const float* __restrict__ gamma,
                                                  const float* __restrict__ beta,
                                                  float* __restrict__ C, int M) {
    __shared__ float As[64 * AS_STRIDE];
    __shared__ float Bs[32 * BS_STRIDE];
    __shared__ float red[2][32][4][2];  // [warpM][rowInHalf][warpN][{sum,sumsq}]

    int tid = threadIdx.x;
    int row0 = blockIdx.x * 64;

    int wid = tid >> 5;
    int lane = tid & 31;
    int warpM = wid & 1;   // 2 warps down M (32 rows each)
    int warpN = wid >> 1;  // 4 warps across N (64 cols each)
    int g = lane >> 2;     // 0..7
    int tig = lane & 3;    // 0..3

    // A global->smem map: 64 rows x 32 k = 512 float4; 2 float4 per thread
    int aRow = tid >> 2;           // 0..63
    int aOff = (tid & 3) * 8;      // float offset in row: 0,8,16,24
    bool aValid = (row0 + aRow) < M;
    const float* Ag = A + (size_t)(row0 + aRow) * D + aOff;

    // B global->smem map: 32 k-rows x 256 cols = 2048 float4; 8 per thread
    int bCol = (tid & 63) * 4;     // 0..252
    int bK0 = tid >> 6;            // 0..3
    const float* Bg = B + (size_t)bK0 * D + bCol;

    float acc[2][8][4];
#pragma unroll
    for (int mt = 0; mt < 2; mt++)
#pragma unroll
        for (int nt = 0; nt < 8; nt++)
#pragma unroll
            for (int c = 0; c < 4; c++) acc[mt][nt][c] = 0.0f;

    for (int k0 = 0; k0 < D; k0 += 32) {
        float4 av[2];
        av[0] = aValid ? *(const float4*)(Ag + k0) : make_float4(0.f, 0.f, 0.f, 0.f);
        av[1] = aValid ? *(const float4*)(Ag + k0 + 4) : make_float4(0.f, 0.f, 0.f, 0.f);
        float4 bv[8];
#pragma unroll
        for (int r = 0; r < 8; r++)
            bv[r] = *(const float4*)(Bg + (size_t)(k0 + r * 4) * D);

        __syncthreads();  // previous tile fully consumed

        float* asp = &As[aRow * AS_STRIDE + aOff];
        asp[0] = __uint_as_float(f2tf(av[0].x));
        asp[1] = __uint_as_float(f2tf(av[0].y));
        asp[2] = __uint_as_float(f2tf(av[0].z));
        asp[3] = __uint_as_float(f2tf(av[0].w));
        asp[4] = __uint_as_float(f2tf(av[1].x));
        asp[5] = __uint_as_float(f2tf(av[1].y));
        asp[6] = __uint_as_float(f2tf(av[1].z));
        asp[7] = __uint_as_float(f2tf(av[1].w));
#pragma unroll
        for (int r = 0; r < 8; r++) {
            float4 t;
            t.x = __uint_as_float(f2tf(bv[r].x));
            t.y = __uint_as_float(f2tf(bv[r].y));
            t.z = __uint_as_float(f2tf(bv[r].z));
            t.w = __uint_as_float(f2tf(bv[r].w));
            *(float4*)&Bs[(bK0 + r * 4) * BS_STRIDE + bCol] = t;
        }
        __syncthreads();

#pragma unroll
        for (int ks = 0; ks < 4; ks++) {
            int kk = ks * 8;
            unsigned af[2][4];
#pragma unroll
            for (int mt = 0; mt < 2; mt++) {
                int r = warpM * 32 + mt * 16 + g;
                const float* ap = &As[r * AS_STRIDE + kk];
                af[mt][0] = __float_as_uint(ap[tig]);
                af[mt][1] = __float_as_uint(ap[8 * AS_STRIDE + tig]);
                af[mt][2] = __float_as_uint(ap[tig + 4]);
                af[mt][3] = __float_as_uint(ap[8 * AS_STRIDE + tig + 4]);
            }
            unsigned bf[8][2];
#pragma unroll
            for (int nt = 0; nt < 8; nt++) {
                int c = warpN * 64 + nt * 8 + g;
                bf[nt][0] = __float_as_uint(Bs[(kk + tig) * BS_STRIDE + c]);
                bf[nt][1] = __float_as_uint(Bs[(kk + tig + 4) * BS_STRIDE + c]);
            }
#pragma unroll
            for (int mt = 0; mt < 2; mt++)
#pragma unroll
                for (int nt = 0; nt < 8; nt++)
                    mma_tf32(acc[mt][nt][0], acc[mt][nt][1], acc[mt][nt][2], acc[mt][nt][3],
                             af[mt][0], af[mt][1], af[mt][2], af[mt][3],
                             bf[nt][0], bf[nt][1]);
        }
    }

    // ---- bias add ----
#pragma unroll
    for (int mt = 0; mt < 2; mt++)
#pragma unroll
        for (int nt = 0; nt < 8; nt++) {
            int col = warpN * 64 + nt * 8 + 2 * tig;
            float2 bb = *(const float2*)(bias + col);
            acc[mt][nt][0] += bb.x;
            acc[mt][nt][1] += bb.y;
            acc[mt][nt][2] += bb.x;
            acc[mt][nt][3] += bb.y;
        }

    if (DO_LN) {
        // ---- per-warp partial sums (64 cols of each of 32 rows per warp) ----
#pragma unroll
        for (int mt = 0; mt < 2; mt++) {
            float s0 = 0.f, q0 = 0.f, s1 = 0.f, q1 = 0.f;
#pragma unroll
            for (int nt = 0; nt < 8; nt++) {
                float a = acc[mt][nt][0], b = acc[mt][nt][1];
                float c = acc[mt][nt][2], d = acc[mt][nt][3];
                s0 += a + b; q0 += a * a + b * b;
                s1 += c + d; q1 += c * c + d * d;
            }
#pragma unroll
            for (int o = 1; o < 4; o <<= 1) {
                s0 += __shfl_xor_sync(0xFFFFFFFFu, s0, o);
                q0 += __shfl_xor_sync(0xFFFFFFFFu, q0, o);
                s1 += __shfl_xor_sync(0xFFFFFFFFu, s1, o);
                q1 += __shfl_xor_sync(0xFFFFFFFFu, q1, o);
            }
            if (tig == 0) {
                red[warpM][mt * 16 + g][warpN][0] = s0;
                red[warpM][mt * 16 + g][warpN][1] = q0;
                red[warpM][mt * 16 + g + 8][warpN][0] = s1;
                red[warpM][mt * 16 + g + 8][warpN][1] = q1;
            }
        }
        __syncthreads();

        // ---- normalize + GELU + store ----
#pragma unroll
        for (int mt = 0; mt < 2; mt++) {
            int rl0 = mt * 16 + g, rl1 = rl0 + 8;
            float S0 = 0.f, Q0 = 0.f, S1 = 0.f, Q1 = 0.f;
#pragma unroll
            for (int w = 0; w < 4; w++) {
                S0 += red[warpM][rl0][w][0];
                Q0 += red[warpM][rl0][w][1];
                S1 += red[warpM][rl1][w][0];
                Q1 += red[warpM][rl1][w][1];
            }
            float mu0 = S0 * (1.0f / D);
            float rs0 = rsqrtf(fmaxf(Q0 * (1.0f / D) - mu0 * mu0, 0.f) + 1e-5f);
            float mu1 = S1 * (1.0f / D);
            float rs1 = rsqrtf(fmaxf(Q1 * (1.0f / D) - mu1 * mu1, 0.f) + 1e-5f);

            int r0 = row0 + warpM * 32 + rl0;
            int r1 = row0 + warpM * 32 + rl1;
#pragma unroll
            for (int nt = 0; nt < 8; nt++) {
                int col = warpN * 64 + nt * 8 + 2 * tig;
                float2 gg = *(const float2*)(gamma + col);
                float2 bb = *(const float2*)(beta + col);
                if (r0 < M) {
                    float t0 = (acc[mt][nt][0] - mu0) * rs0 * gg.x + bb.x;
                    float t1 = (acc[mt][nt][1] - mu0) * rs0 * gg.y + bb.y;
                    float2 o = make_float2(gelu_exact(t0), gelu_exact(t1));
                    *(float2*)(C + (size_t)r0 * D + col) = o;
                }
                if (r1 < M) {
                    float t2 = (acc[mt][nt][2] - mu1) * rs1 * gg.x + bb.x;
                    float t3 = (acc[mt][nt][3] - mu1) * rs1 * gg.y + bb.y;
                    float2 o = make_float2(gelu_exact(t2), gelu_exact(t3));
                    *(float2*)(C + (size_t)r1 * D + col) = o;
                }
            }
        }
    } else {
        // ---- plain bias epilogue ----
#pragma unroll
        for (int mt = 0; mt < 2; mt++) {
            int r0 = row0 + warpM * 32 + mt * 16 + g;
            int r1 = r0 + 8;
#pragma unroll
            for (int nt = 0; nt < 8; nt++) {
                int col = warpN * 64 + nt * 8 + 2 * tig;
                if (r0 < M) {
                    float2 o = make_float2(acc[mt][nt][0], acc[mt][nt][1]);
                    *(float2*)(C + (size_t)r0 * D + col) = o;
                }
                if (r1 < M) {
                    float2 o = make_float2(acc[mt][nt][2], acc[mt][nt][3]);
                    *(float2*)(C + (size_t)r1 * D + col) = o;
                }
            }
        }
    }
}

// ---------------------------------------------------------------------------
extern "C" void kernel_launch(void* const* d_in, const int* in_sizes, int n_in,
                              void* d_out, int out_size) {
    const float* xin = (const float*)d_in[0];
    const int* srcI  = (const int*)d_in[1];
    const int* dstI  = (const int*)d_in[2];
    const float* ew  = (const float*)d_in[3];
    const float* W1  = (const float*)d_in[4];
    const float* b1  = (const float*)d_in[5];
    const float* g1  = (const float*)d_in[6];
    const float* be1 = (const float*)d_in[7];
    const float* W2  = (const float*)d_in[8];
    const float* b2  = (const float*)d_in[9];
    const float* g2  = (const float*)d_in[10];
    const float* be2 = (const float*)d_in[11];
    const float* Wp  = (const float*)d_in[12];
    const float* bp  = (const float*)d_in[13];

    int n  = in_sizes[0] / D;   // 50000
    int nE = in_sizes[1];       // 800000

    float *agg, *xb, *ewc;
    int *deg, *rowptr, *wptr, *esrc;
    cudaGetSymbolAddress((void**)&agg, g_agg);
    cudaGetSymbolAddress((void**)&xb, g_x);
    cudaGetSymbolAddress((void**)&deg, g_deg);
    cudaGetSymbolAddress((void**)&rowptr, g_rowptr);
    cudaGetSymbolAddress((void**)&wptr, g_wptr);
    cudaGetSymbolAddress((void**)&esrc, g_esrc);
    cudaGetSymbolAddress((void**)&ewc, g_ew);

    int gmBlocks = (n + 63) / 64;
    int gaBlocks = (n + 7) / 8;

    // ----- CSR build (once per launch; graph static within a call) -----
    zero_int<<<(n + 255) / 256, 256>>>(deg, n);
    hist_deg<<<1024, 256>>>(dstI, deg, nE);
    scan_deg<<<1, SCAN_T>>>(deg, rowptr, wptr, n);
    fill_csr<<<1024, 256>>>(srcI, dstI, ew, wptr, esrc, ewc, nE);

    // ----- Layer 1 -----
    gather_agg<<<gaBlocks, 256>>>(xin, rowptr, esrc, ewc, agg, n);
    gemm_fused<true><<<gmBlocks, 256>>>(agg, W1, b1, g1, be1, xb, n);

    // ----- Layer 2 -----
    gather_agg<<<gaBlocks, 256>>>(xb, rowptr, esrc, ewc, agg, n);
    gemm_fused<true><<<gmBlocks, 256>>>(agg, W2, b2, g2, be2, xb, n);

    // ----- Output projection -----
    gemm_fused<false><<<gmBlocks, 256>>>(xb, Wp, bp, nullptr, nullptr, (float*)d_out, n);
}

// round 8
// speedup vs baseline: 2.4315x; 1.0460x over previous
#include <cuda_runtime.h>
#include <cstdint>
#include <math.h>

#define D 256
#define MAXN 50048   // 50000 rounded up to 128
#define MAXE 1048576 // >= 800000

// Scratch (allocation-free rule: __device__ globals)
__device__ float g_agg[(size_t)MAXN * D];
__device__ float g_x[(size_t)MAXN * D];
__device__ int   g_deg[MAXN + 1];
__device__ int   g_rowptr[MAXN + 1];
__device__ int   g_wptr[MAXN + 1];
__device__ int   g_esrc[MAXE];
__device__ float g_ew[MAXE];

// ---------------------------------------------------------------------------
// CSR build: zero -> histogram -> scan -> fill  (1 thread/edge for MLP)
// ---------------------------------------------------------------------------
__global__ void zero_int(int* p, int n) {
    int i = blockIdx.x * blockDim.x + threadIdx.x;
    if (i < n) p[i] = 0;
}

__global__ void hist_deg(const int* __restrict__ dstI, int* __restrict__ deg, int nE) {
    int i = blockIdx.x * blockDim.x + threadIdx.x;
    if (i < nE) atomicAdd(&deg[dstI[i]], 1);
}

#define SCAN_T 1024
__global__ __launch_bounds__(SCAN_T) void scan_deg(const int* __restrict__ deg,
                                                   int* __restrict__ rowptr,
                                                   int* __restrict__ wptr, int n) {
    __shared__ int sums[SCAN_T];
    int t = threadIdx.x;
    int chunk = (n + SCAN_T - 1) / SCAN_T;
    int beg = t * chunk;
    int end = min(beg + chunk, n);
    int s = 0;
    for (int i = beg; i < end; i++) s += deg[i];
    sums[t] = s;
    __syncthreads();
    for (int o = 1; o < SCAN_T; o <<= 1) {
        int v = (t >= o) ? sums[t - o] : 0;
        __syncthreads();
        sums[t] += v;
        __syncthreads();
    }
    int base = (t == 0) ? 0 : sums[t - 1];
    for (int i = beg; i < end; i++) {
        rowptr[i] = base;
        wptr[i] = base;
        base += deg[i];
    }
    if (t == 0) rowptr[n] = sums[SCAN_T - 1];
}

__global__ void fill_csr(const int* __restrict__ srcI, const int* __restrict__ dstI,
                         const float* __restrict__ ew, int* __restrict__ wptr,
                         int* __restrict__ esrc, float* __restrict__ ewOut, int nE) {
    int i = blockIdx.x * blockDim.x + threadIdx.x;
    if (i < nE) {
        int pos = atomicAdd(&wptr[dstI[i]], 1);
        esrc[pos] = srcI[i];
        ewOut[pos] = ew[i];
    }
}

// ---------------------------------------------------------------------------
// Gather: agg[i] = x[i] + sum_e w_e * x[src_e]. One warp per node, no atomics.
// ---------------------------------------------------------------------------
__device__ __forceinline__ void fma4(float4& a, float w, const float4& v) {
    a.x = fmaf(w, v.x, a.x);
    a.y = fmaf(w, v.y, a.y);
    a.z = fmaf(w, v.z, a.z);
    a.w = fmaf(w, v.w, a.w);
}

__global__ __launch_bounds__(256) void gather_agg(const float* __restrict__ x,
                                                  const int* __restrict__ rowptr,
                                                  const int* __restrict__ esrc,
                                                  const float* __restrict__ ew,
                                                  float* __restrict__ agg, int n) {
    int warp = (blockIdx.x * blockDim.x + threadIdx.x) >> 5;
    if (warp >= n) return;
    int lane = threadIdx.x & 31;

    const float4* xr = (const float4*)(x + (size_t)warp * D);
    float4 a0 = xr[lane];
    float4 a1 = xr[lane + 32];

    int e = rowptr[warp];
    int end = rowptr[warp + 1];
    for (; e + 2 <= end; e += 2) {
        int s0 = esrc[e], s1 = esrc[e + 1];
        float w0 = ew[e], w1 = ew[e + 1];
        const float4* p0 = (const float4*)(x + (size_t)s0 * D);
        const float4* p1 = (const float4*)(x + (size_t)s1 * D);
        float4 v00 = p0[lane], v01 = p0[lane + 32];
        float4 v10 = p1[lane], v11 = p1[lane + 32];
        fma4(a0, w0, v00);
        fma4(a1, w0, v01);
        fma4(a0, w1, v10);
        fma4(a1, w1, v11);
    }
    if (e < end) {
        int s0 = esrc[e];
        float w0 = ew[e];
        const float4* p0 = (const float4*)(x + (size_t)s0 * D);
        fma4(a0, w0, p0[lane]);
        fma4(a1, w0, p0[lane + 32]);
    }

    float4* ar = (float4*)(agg + (size_t)warp * D);
    ar[lane] = a0;
    ar[lane + 32] = a1;
}

// ---------------------------------------------------------------------------
// Fused TF32 GEMM (+bias, optional LayerNorm+GELU epilogue)
// cp.async double-buffered mainloop. BM=64, BN=256, BK=32.
// 8 warps as 2(M) x 4(N); warp tile 32x64 via m16n8k8 tf32 mma.
// ---------------------------------------------------------------------------
__device__ __forceinline__ unsigned f2tf(float f) {
    unsigned r;
    asm("cvt.rna.tf32.f32 %0, %1;" : "=r"(r) : "f"(f));
    return r;
}

__device__ __forceinline__ void mma_tf32(float& d0, float& d1, float& d2, float& d3,
                                         unsigned a0, unsigned a1, unsigned a2, unsigned a3,
                                         unsigned b0, unsigned b1) {
    asm volatile(
        "mma.sync.aligned.m16n8k8.row.col.f32.tf32.tf32.f32 "
        "{%0,%1,%2,%3}, {%4,%5,%6,%7}, {%8,%9}, {%0,%1,%2,%3};"
        : "+f"(d0), "+f"(d1), "+f"(d2), "+f"(d3)
        : "r"(a0), "r"(a1), "r"(a2), "r"(a3), "r"(b0), "r"(b1));
}

__device__ __forceinline__ float gelu_exact(float t) {
    return 0.5f * t * (1.0f + erff(t * 0.70710678118654752f));
}

__device__ __forceinline__ void cp_async16(unsigned int s, const void* g) {
    asm volatile("cp.async.cg.shared.global [%0], [%1], 16;" :: "r"(s), "l"(g));
}
__device__ __forceinline__ void cp_commit() {
    asm volatile("cp.async.commit_group;");
}
template <int N>
__device__ __forceinline__ void cp_wait() {
    asm volatile("cp.async.wait_group %0;" :: "n"(N));
}

#define AS_STRIDE 36   // conflict-free A frag loads (bank = 4g + tig)
#define BS_STRIDE 264  // conflict-free B frag loads (bank = 8k' + g)
#define AS_FLOATS (64 * AS_STRIDE)   // 2304
#define BS_FLOATS (32 * BS_STRIDE)   // 8448
#define RED_FLOATS 512
#define GEMM_SMEM_BYTES ((2 * AS_FLOATS + 2 * BS_FLOATS + RED_FLOATS) * 4)  // 88064

template <bool DO_LN>
__global__ __launch_bounds__(256) void gemm_fused(const float* __restrict__ A,
                                                  const float* __restrict__ B,
                                                  const float* __restrict__ bias,
                                                  const float* __restrict__ gamma,
                                                  const float* __restrict__ beta,
                                                  float* __restrict__ C, int M) {
    extern __shared__ float smem[];
    float* Asm[2] = {smem, smem + AS_FLOATS};
    float* Bsm[2] = {smem + 2 * AS_FLOATS, smem + 2 * AS_FLOATS + BS_FLOATS};
    float* red = smem + 2 * AS_FLOATS + 2 * BS_FLOATS;  // [warpM][32][4][2]

    int tid = threadIdx.x;
    int row0 = blockIdx.x * 64;

    int wid = tid >> 5;
    int lane = tid & 31;
    int warpM = wid & 1;   // 2 warps down M (32 rows each)
    int warpN = wid >> 1;  // 4 warps across N (64 cols each)
    int g = lane >> 2;     // 0..7
    int tig = lane & 3;    // 0..3

    // A gmem->smem: 64 rows x 32 k; thread loads 8 floats of one row (2x cp16)
    int aRow = tid >> 2;           // 0..63
    int aOff = (tid & 3) * 8;      // 0,8,16,24
    int aRowG = min(row0 + aRow, M - 1);  // clamp; invalid rows masked at store
    const float* Ag = A + (size_t)aRowG * D + aOff;
    unsigned int aS[2];
    aS[0] = (unsigned int)__cvta_generic_to_shared(Asm[0] + aRow * AS_STRIDE + aOff);
    aS[1] = (unsigned int)__cvta_generic_to_shared(Asm[1] + aRow * AS_STRIDE + aOff);

    // B gmem->smem: 32 k-rows x 256 cols; thread loads 8 rows x 4 floats
    int bCol = (tid & 63) * 4;     // 0..252
    int bK0 = tid >> 6;            // 0..3
    const float* Bg = B + (size_t)bK0 * D + bCol;
    unsigned int bS[2];
    bS[0] = (unsigned int)__cvta_generic_to_shared(Bsm[0] + bK0 * BS_STRIDE + bCol);
    bS[1] = (unsigned int)__cvta_generic_to_shared(Bsm[1] + bK0 * BS_STRIDE + bCol);

    float acc[2][8][4];
#pragma unroll
    for (int mt = 0; mt < 2; mt++)
#pragma unroll
        for (int nt = 0; nt < 8; nt++)
#pragma unroll
            for (int c = 0; c < 4; c++) acc[mt][nt][c] = 0.0f;

    // prologue: issue tiles 0 and 1
#pragma unroll
    for (int kt = 0; kt < 2; kt++) {
        int k0 = kt * 32;
        cp_async16(aS[kt], Ag + k0);
        cp_async16(aS[kt] + 16, Ag + k0 + 4);
#pragma unroll
        for (int r = 0; r < 8; r++)
            cp_async16(bS[kt] + r * 4 * BS_STRIDE * 4, Bg + (size_t)(k0 + r * 4) * D);
        cp_commit();
    }

#pragma unroll
    for (int kt = 0; kt < 8; kt++) {
        if (kt < 7) cp_wait<1>(); else cp_wait<0>();
        __syncthreads();
        const float* Ab = Asm[kt & 1];
        const float* Bb = Bsm[kt & 1];

#pragma unroll
        for (int ks = 0; ks < 4; ks++) {
            int kk = ks * 8;
            unsigned af[2][4];
#pragma unroll
            for (int mt = 0; mt < 2; mt++) {
                int r = warpM * 32 + mt * 16 + g;
                const float* ap = &Ab[r * AS_STRIDE + kk];
                af[mt][0] = f2tf(ap[tig]);
                af[mt][1] = f2tf(ap[8 * AS_STRIDE + tig]);
                af[mt][2] = f2tf(ap[tig + 4]);
                af[mt][3] = f2tf(ap[8 * AS_STRIDE + tig + 4]);
            }
            unsigned bf[8][2];
#pragma unroll
            for (int nt = 0; nt < 8; nt++) {
                int c = warpN * 64 + nt * 8 + g;
                bf[nt][0] = f2tf(Bb[(kk + tig) * BS_STRIDE + c]);
                bf[nt][1] = f2tf(Bb[(kk + tig + 4) * BS_STRIDE + c]);
            }
#pragma unroll
            for (int mt = 0; mt < 2; mt++)
#pragma unroll
                for (int nt = 0; nt < 8; nt++)
                    mma_tf32(acc[mt][nt][0], acc[mt][nt][1], acc[mt][nt][2], acc[mt][nt][3],
                             af[mt][0], af[mt][1], af[mt][2], af[mt][3],
                             bf[nt][0], bf[nt][1]);
        }
        __syncthreads();  // all warps done reading buf[kt&1]

        if (kt + 2 < 8) {
            int k0 = (kt + 2) * 32;
            int b = kt & 1;  // tile kt+2 reuses buffer of tile kt
            cp_async16(aS[b], Ag + k0);
            cp_async16(aS[b] + 16, Ag + k0 + 4);
#pragma unroll
            for (int r = 0; r < 8; r++)
                cp_async16(bS[b] + r * 4 * BS_STRIDE * 4, Bg + (size_t)(k0 + r * 4) * D);
            cp_commit();
        }
    }

    // ---- bias add ----
#pragma unroll
    for (int mt = 0; mt < 2; mt++)
#pragma unroll
        for (int nt = 0; nt < 8; nt++) {
            int col = warpN * 64 + nt * 8 + 2 * tig;
            float2 bb = *(const float2*)(bias + col);
            acc[mt][nt][0] += bb.x;
            acc[mt][nt][1] += bb.y;
            acc[mt][nt][2] += bb.x;
            acc[mt][nt][3] += bb.y;
        }

    if (DO_LN) {
        // red[warpM][row][warpN][c] -> ((warpM*32 + row)*4 + warpN)*2 + c
#pragma unroll
        for (int mt = 0; mt < 2; mt++) {
            float s0 = 0.f, q0 = 0.f, s1 = 0.f, q1 = 0.f;
#pragma unroll
            for (int nt = 0; nt < 8; nt++) {
                float a = acc[mt][nt][0], b = acc[mt][nt][1];
                float c = acc[mt][nt][2], d = acc[mt][nt][3];
                s0 += a + b; q0 += a * a + b * b;
                s1 += c + d; q1 += c * c + d * d;
            }
#pragma unroll
            for (int o = 1; o < 4; o <<= 1) {
                s0 += __shfl_xor_sync(0xFFFFFFFFu, s0, o);
                q0 += __shfl_xor_sync(0xFFFFFFFFu, q0, o);
                s1 += __shfl_xor_sync(0xFFFFFFFFu, s1, o);
                q1 += __shfl_xor_sync(0xFFFFFFFFu, q1, o);
            }
            if (tig == 0) {
                int r0 = mt * 16 + g, r1 = r0 + 8;
                red[((warpM * 32 + r0) * 4 + warpN) * 2 + 0] = s0;
                red[((warpM * 32 + r0) * 4 + warpN) * 2 + 1] = q0;
                red[((warpM * 32 + r1) * 4 + warpN) * 2 + 0] = s1;
                red[((warpM * 32 + r1) * 4 + warpN) * 2 + 1] = q1;
            }
        }
        __syncthreads();

#pragma unroll
        for (int mt = 0; mt < 2; mt++) {
            int rl0 = mt * 16 + g, rl1 = rl0 + 8;
            float S0 = 0.f, Q0 = 0.f, S1 = 0.f, Q1 = 0.f;
#pragma unroll
            for (int w = 0; w < 4; w++) {
                S0 += red[((warpM * 32 + rl0) * 4 + w) * 2 + 0];
                Q0 += red[((warpM * 32 + rl0) * 4 + w) * 2 + 1];
                S1 += red[((warpM * 32 + rl1) * 4 + w) * 2 + 0];
                Q1 += red[((warpM * 32 + rl1) * 4 + w) * 2 + 1];
            }
            float mu0 = S0 * (1.0f / D);
            float rs0 = rsqrtf(fmaxf(Q0 * (1.0f / D) - mu0 * mu0, 0.f) + 1e-5f);
            float mu1 = S1 * (1.0f / D);
            float rs1 = rsqrtf(fmaxf(Q1 * (1.0f / D) - mu1 * mu1, 0.f) + 1e-5f);

            int r0 = row0 + warpM * 32 + rl0;
            int r1 = row0 + warpM * 32 + rl1;
#pragma unroll
            for (int nt = 0; nt < 8; nt++) {
                int col = warpN * 64 + nt * 8 + 2 * tig;
                float2 gg = *(const float2*)(gamma + col);
                float2 bb = *(const float2*)(beta + col);
                if (r0 < M) {
                    float t0 = (acc[mt][nt][0] - mu0) * rs0 * gg.x + bb.x;
                    float t1 = (acc[mt][nt][1] - mu0) * rs0 * gg.y + bb.y;
                    float2 o = make_float2(gelu_exact(t0), gelu_exact(t1));
                    *(float2*)(C + (size_t)r0 * D + col) = o;
                }
                if (r1 < M) {
                    float t2 = (acc[mt][nt][2] - mu1) * rs1 * gg.x + bb.x;
                    float t3 = (acc[mt][nt][3] - mu1) * rs1 * gg.y + bb.y;
                    float2 o = make_float2(gelu_exact(t2), gelu_exact(t3));
                    *(float2*)(C + (size_t)r1 * D + col) = o;
                }
            }
        }
    } else {
#pragma unroll
        for (int mt = 0; mt < 2; mt++) {
            int r0 = row0 + warpM * 32 + mt * 16 + g;
            int r1 = r0 + 8;
#pragma unroll
            for (int nt = 0; nt < 8; nt++) {
                int col = warpN * 64 + nt * 8 + 2 * tig;
                if (r0 < M) {
                    float2 o = make_float2(acc[mt][nt][0], acc[mt][nt][1]);
                    *(float2*)(C + (size_t)r0 * D + col) = o;
                }
                if (r1 < M) {
                    float2 o = make_float2(acc[mt][nt][2], acc[mt][nt][3]);
                    *(float2*)(C + (size_t)r1 * D + col) = o;
                }
            }
        }
    }
}

// ---------------------------------------------------------------------------
extern "C" void kernel_launch(void* const* d_in, const int* in_sizes, int n_in,
                              void* d_out, int out_size) {
    const float* xin = (const float*)d_in[0];
    const int* srcI  = (const int*)d_in[1];
    const int* dstI  = (const int*)d_in[2];
    const float* ew  = (const float*)d_in[3];
    const float* W1  = (const float*)d_in[4];
    const float* b1  = (const float*)d_in[5];
    const float* g1  = (const float*)d_in[6];
    const float* be1 = (const float*)d_in[7];
    const float* W2  = (const float*)d_in[8];
    const float* b2  = (const float*)d_in[9];
    const float* g2  = (const float*)d_in[10];
    const float* be2 = (const float*)d_in[11];
    const float* Wp  = (const float*)d_in[12];
    const float* bp  = (const float*)d_in[13];

    int n  = in_sizes[0] / D;   // 50000
    int nE = in_sizes[1];       // 800000

    float *agg, *xb, *ewc;
    int *deg, *rowptr, *wptr, *esrc;
    cudaGetSymbolAddress((void**)&agg, g_agg);
    cudaGetSymbolAddress((void**)&xb, g_x);
    cudaGetSymbolAddress((void**)&deg, g_deg);
    cudaGetSymbolAddress((void**)&rowptr, g_rowptr);
    cudaGetSymbolAddress((void**)&wptr, g_wptr);
    cudaGetSymbolAddress((void**)&esrc, g_esrc);
    cudaGetSymbolAddress((void**)&ewc, g_ew);

    cudaFuncSetAttribute(gemm_fused<true>, cudaFuncAttributeMaxDynamicSharedMemorySize,
                         GEMM_SMEM_BYTES);
    cudaFuncSetAttribute(gemm_fused<false>, cudaFuncAttributeMaxDynamicSharedMemorySize,
                         GEMM_SMEM_BYTES);

    int gmBlocks = (n + 63) / 64;
    int gaBlocks = (n + 7) / 8;
    int eBlocks = (nE + 255) / 256;

    // ----- CSR build (once per launch; graph static within a call) -----
    zero_int<<<(n + 255) / 256, 256>>>(deg, n);
    hist_deg<<<eBlocks, 256>>>(dstI, deg, nE);
    scan_deg<<<1, SCAN_T>>>(deg, rowptr, wptr, n);
    fill_csr<<<eBlocks, 256>>>(srcI, dstI, ew, wptr, esrc, ewc, nE);

    // ----- Layer 1 -----
    gather_agg<<<gaBlocks, 256>>>(xin, rowptr, esrc, ewc, agg, n);
    gemm_fused<true><<<gmBlocks, 256, GEMM_SMEM_BYTES>>>(agg, W1, b1, g1, be1, xb, n);

    // ----- Layer 2 -----
    gather_agg<<<gaBlocks, 256>>>(xb, rowptr, esrc, ewc, agg, n);
    gemm_fused<true><<<gmBlocks, 256, GEMM_SMEM_BYTES>>>(agg, W2, b2, g2, be2, xb, n);

    // ----- Output projection -----
    gemm_fused<false><<<gmBlocks, 256, GEMM_SMEM_BYTES>>>(xb, Wp, bp, nullptr, nullptr,
                                                          (float*)d_out, n);
}

// round 9
// speedup vs baseline: 2.5845x; 1.0630x over previous
#include <cuda_runtime.h>
#include <cstdint>
#include <math.h>

#define D 256
#define MAXN 50048   // 50000 rounded up to 128
#define MAXE 1048576 // >= 800000

// Scratch (allocation-free rule: __device__ globals)
__device__ float g_agg[(size_t)MAXN * D];
__device__ float g_x[(size_t)MAXN * D];
__device__ float g_wt[3 * D * D];   // tf32-rounded W1|W2|Wp
__device__ int   g_deg[MAXN + 1];
__device__ int   g_rowptr[MAXN + 1];
__device__ int   g_wptr[MAXN + 1];
__device__ int   g_esrc[MAXE];
__device__ float g_ew[MAXE];

__device__ __forceinline__ unsigned f2tf(float f) {
    unsigned r;
    asm("cvt.rna.tf32.f32 %0, %1;" : "=r"(r) : "f"(f));
    return r;
}
__device__ __forceinline__ float f2tf_f(float f) { return __uint_as_float(f2tf(f)); }

// ---------------------------------------------------------------------------
// Round three weight matrices to tf32 once per launch (inputs concatenated)
// ---------------------------------------------------------------------------
__global__ void round_weights(const float* __restrict__ w1, const float* __restrict__ w2,
                              const float* __restrict__ wp, float* __restrict__ out) {
    int i = blockIdx.x * blockDim.x + threadIdx.x;  // 0 .. 3*65536/4-1 (float4)
    const float* src = (i < 16384) ? w1 : (i < 32768) ? w2 : wp;
    int j = i & 16383;
    float4 v = ((const float4*)src)[j];
    float4 o;
    o.x = f2tf_f(v.x); o.y = f2tf_f(v.y); o.z = f2tf_f(v.z); o.w = f2tf_f(v.w);
    ((float4*)out)[i] = o;
}

// ---------------------------------------------------------------------------
// CSR build: zero -> histogram -> scan -> fill  (1 thread/edge for MLP)
// ---------------------------------------------------------------------------
__global__ void zero_int(int* p, int n) {
    int i = blockIdx.x * blockDim.x + threadIdx.x;
    if (i < n) p[i] = 0;
}

__global__ void hist_deg(const int* __restrict__ dstI, int* __restrict__ deg, int nE) {
    int i = blockIdx.x * blockDim.x + threadIdx.x;
    if (i < nE) atomicAdd(&deg[dstI[i]], 1);
}

#define SCAN_T 1024
__global__ __launch_bounds__(SCAN_T) void scan_deg(const int* __restrict__ deg,
                                                   int* __restrict__ rowptr,
                                                   int* __restrict__ wptr, int n) {
    __shared__ int sums[SCAN_T];
    int t = threadIdx.x;
    int chunk = (n + SCAN_T - 1) / SCAN_T;
    int beg = t * chunk;
    int end = min(beg + chunk, n);
    int s = 0;
    for (int i = beg; i < end; i++) s += deg[i];
    sums[t] = s;
    __syncthreads();
    for (int o = 1; o < SCAN_T; o <<= 1) {
        int v = (t >= o) ? sums[t - o] : 0;
        __syncthreads();
        sums[t] += v;
        __syncthreads();
    }
    int base = (t == 0) ? 0 : sums[t - 1];
    for (int i = beg; i < end; i++) {
        rowptr[i] = base;
        wptr[i] = base;
        base += deg[i];
    }
    if (t == 0) rowptr[n] = sums[SCAN_T - 1];
}

__global__ void fill_csr(const int* __restrict__ srcI, const int* __restrict__ dstI,
                         const float* __restrict__ ew, int* __restrict__ wptr,
                         int* __restrict__ esrc, float* __restrict__ ewOut, int nE) {
    int i = blockIdx.x * blockDim.x + threadIdx.x;
    if (i < nE) {
        int pos = atomicAdd(&wptr[dstI[i]], 1);
        esrc[pos] = srcI[i];
        ewOut[pos] = ew[i];
    }
}

// ---------------------------------------------------------------------------
// Gather: agg[i] = x[i] + sum_e w_e * x[src_e]. One warp per node, no atomics.
// Output rounded to tf32 (GEMM consumes it without in-loop cvt).
// ---------------------------------------------------------------------------
__device__ __forceinline__ void fma4(float4& a, float w, const float4& v) {
    a.x = fmaf(w, v.x, a.x);
    a.y = fmaf(w, v.y, a.y);
    a.z = fmaf(w, v.z, a.z);
    a.w = fmaf(w, v.w, a.w);
}

__global__ __launch_bounds__(256) void gather_agg(const float* __restrict__ x,
                                                  const int* __restrict__ rowptr,
                                                  const int* __restrict__ esrc,
                                                  const float* __restrict__ ew,
                                                  float* __restrict__ agg, int n) {
    int warp = (blockIdx.x * blockDim.x + threadIdx.x) >> 5;
    if (warp >= n) return;
    int lane = threadIdx.x & 31;

    const float4* xr = (const float4*)(x + (size_t)warp * D);
    float4 a0 = xr[lane];
    float4 a1 = xr[lane + 32];

    int e = rowptr[warp];
    int end = rowptr[warp + 1];
    for (; e + 2 <= end; e += 2) {
        int s0 = esrc[e], s1 = esrc[e + 1];
        float w0 = ew[e], w1 = ew[e + 1];
        const float4* p0 = (const float4*)(x + (size_t)s0 * D);
        const float4* p1 = (const float4*)(x + (size_t)s1 * D);
        float4 v00 = p0[lane], v01 = p0[lane + 32];
        float4 v10 = p1[lane], v11 = p1[lane + 32];
        fma4(a0, w0, v00);
        fma4(a1, w0, v01);
        fma4(a0, w1, v10);
        fma4(a1, w1, v11);
    }
    if (e < end) {
        int s0 = esrc[e];
        float w0 = ew[e];
        const float4* p0 = (const float4*)(x + (size_t)s0 * D);
        fma4(a0, w0, p0[lane]);
        fma4(a1, w0, p0[lane + 32]);
    }

    a0.x = f2tf_f(a0.x); a0.y = f2tf_f(a0.y); a0.z = f2tf_f(a0.z); a0.w = f2tf_f(a0.w);
    a1.x = f2tf_f(a1.x); a1.y = f2tf_f(a1.y); a1.z = f2tf_f(a1.z); a1.w = f2tf_f(a1.w);

    float4* ar = (float4*)(agg + (size_t)warp * D);
    ar[lane] = a0;
    ar[lane + 32] = a1;
}

// ---------------------------------------------------------------------------
// Fused TF32 GEMM (+bias, optional LayerNorm+GELU epilogue)
// Inputs already tf32-rounded in gmem -> no cvt in mainloop.
// cp.async double-buffered, ONE __syncthreads per k-tile.
// BM=64, BN=256, BK=32; 8 warps as 2(M) x 4(N); m16n8k8 tf32 mma.
// ---------------------------------------------------------------------------
__device__ __forceinline__ void mma_tf32(float& d0, float& d1, float& d2, float& d3,
                                         unsigned a0, unsigned a1, unsigned a2, unsigned a3,
                                         unsigned b0, unsigned b1) {
    asm volatile(
        "mma.sync.aligned.m16n8k8.row.col.f32.tf32.tf32.f32 "
        "{%0,%1,%2,%3}, {%4,%5,%6,%7}, {%8,%9}, {%0,%1,%2,%3};"
        : "+f"(d0), "+f"(d1), "+f"(d2), "+f"(d3)
        : "r"(a0), "r"(a1), "r"(a2), "r"(a3), "r"(b0), "r"(b1));
}

__device__ __forceinline__ float gelu_exact(float t) {
    return 0.5f * t * (1.0f + erff(t * 0.70710678118654752f));
}

__device__ __forceinline__ void cp_async16(unsigned int s, const void* g) {
    asm volatile("cp.async.cg.shared.global [%0], [%1], 16;" :: "r"(s), "l"(g));
}
__device__ __forceinline__ void cp_commit() {
    asm volatile("cp.async.commit_group;");
}
template <int N>
__device__ __forceinline__ void cp_wait() {
    asm volatile("cp.async.wait_group %0;" :: "n"(N));
}

#define AS_STRIDE 36   // conflict-free A frag loads (bank = 4g + tig)
#define BS_STRIDE 264  // conflict-free B frag loads (bank = 8k' + g)
#define AS_FLOATS (64 * AS_STRIDE)   // 2304
#define BS_FLOATS (32 * BS_STRIDE)   // 8448
#define RED_FLOATS 512
#define GEMM_SMEM_BYTES ((2 * AS_FLOATS + 2 * BS_FLOATS + RED_FLOATS) * 4)  // 88064

template <bool DO_LN>
__global__ __launch_bounds__(256) void gemm_fused(const float* __restrict__ A,
                                                  const float* __restrict__ B,
                                                  const float* __restrict__ bias,
                                                  const float* __restrict__ gamma,
                                                  const float* __restrict__ beta,
                                                  float* __restrict__ C, int M) {
    extern __shared__ float smem[];
    float* Asm[2] = {smem, smem + AS_FLOATS};
    float* Bsm[2] = {smem + 2 * AS_FLOATS, smem + 2 * AS_FLOATS + BS_FLOATS};
    float* red = smem + 2 * AS_FLOATS + 2 * BS_FLOATS;

    int tid = threadIdx.x;
    int row0 = blockIdx.x * 64;

    int wid = tid >> 5;
    int lane = tid & 31;
    int warpM = wid & 1;   // 2 warps down M (32 rows each)
    int warpN = wid >> 1;  // 4 warps across N (64 cols each)
    int g = lane >> 2;     // 0..7
    int tig = lane & 3;    // 0..3

    // A gmem->smem: 64 rows x 32 k; thread copies 8 floats of one row (2x cp16)
    int aRow = tid >> 2;
    int aOff = (tid & 3) * 8;
    int aRowG = min(row0 + aRow, M - 1);  // clamp; invalid rows masked at store
    const float* Ag = A + (size_t)aRowG * D + aOff;
    unsigned int aS[2];
    aS[0] = (unsigned int)__cvta_generic_to_shared(Asm[0] + aRow * AS_STRIDE + aOff);
    aS[1] = (unsigned int)__cvta_generic_to_shared(Asm[1] + aRow * AS_STRIDE + aOff);

    // B gmem->smem: 32 k-rows x 256 cols; thread copies 8 rows x 4 floats
    int bCol = (tid & 63) * 4;
    int bK0 = tid >> 6;
    const float* Bg = B + (size_t)bK0 * D + bCol;
    unsigned int bS[2];
    bS[0] = (unsigned int)__cvta_generic_to_shared(Bsm[0] + bK0 * BS_STRIDE + bCol);
    bS[1] = (unsigned int)__cvta_generic_to_shared(Bsm[1] + bK0 * BS_STRIDE + bCol);

    float acc[2][8][4];
#pragma unroll
    for (int mt = 0; mt < 2; mt++)
#pragma unroll
        for (int nt = 0; nt < 8; nt++)
#pragma unroll
            for (int c = 0; c < 4; c++) acc[mt][nt][c] = 0.0f;

    // prologue: issue tile 0
    {
        cp_async16(aS[0], Ag);
        cp_async16(aS[0] + 16, Ag + 4);
#pragma unroll
        for (int r = 0; r < 8; r++)
            cp_async16(bS[0] + r * 4 * BS_STRIDE * 4, Bg + (size_t)(r * 4) * D);
        cp_commit();
    }

#pragma unroll
    for (int kt = 0; kt < 8; kt++) {
        cp_wait<0>();
        __syncthreads();  // proves: tile kt landed AND all warps done with tile kt-1

        if (kt + 1 < 8) {  // copy(kt+1) overlaps compute(kt)
            int k0 = (kt + 1) * 32;
            int b = (kt + 1) & 1;
            cp_async16(aS[b], Ag + k0);
            cp_async16(aS[b] + 16, Ag + k0 + 4);
#pragma unroll
            for (int r = 0; r < 8; r++)
                cp_async16(bS[b] + r * 4 * BS_STRIDE * 4, Bg + (size_t)(k0 + r * 4) * D);
            cp_commit();
        }

        const float* Ab = Asm[kt & 1];
        const float* Bb = Bsm[kt & 1];
#pragma unroll
        for (int ks = 0; ks < 4; ks++) {
            int kk = ks * 8;
            unsigned af[2][4];
#pragma unroll
            for (int mt = 0; mt < 2; mt++) {
                int r = warpM * 32 + mt * 16 + g;
                const float* ap = &Ab[r * AS_STRIDE + kk];
                af[mt][0] = __float_as_uint(ap[tig]);
                af[mt][1] = __float_as_uint(ap[8 * AS_STRIDE + tig]);
                af[mt][2] = __float_as_uint(ap[tig + 4]);
                af[mt][3] = __float_as_uint(ap[8 * AS_STRIDE + tig + 4]);
            }
            unsigned bf[8][2];
#pragma unroll
            for (int nt = 0; nt < 8; nt++) {
                int c = warpN * 64 + nt * 8 + g;
                bf[nt][0] = __float_as_uint(Bb[(kk + tig) * BS_STRIDE + c]);
                bf[nt][1] = __float_as_uint(Bb[(kk + tig + 4) * BS_STRIDE + c]);
            }
#pragma unroll
            for (int mt = 0; mt < 2; mt++)
#pragma unroll
                for (int nt = 0; nt < 8; nt++)
                    mma_tf32(acc[mt][nt][0], acc[mt][nt][1], acc[mt][nt][2], acc[mt][nt][3],
                             af[mt][0], af[mt][1], af[mt][2], af[mt][3],
                             bf[nt][0], bf[nt][1]);
        }
    }

    // ---- bias add ----
#pragma unroll
    for (int mt = 0; mt < 2; mt++)
#pragma unroll
        for (int nt = 0; nt < 8; nt++) {
            int col = warpN * 64 + nt * 8 + 2 * tig;
            float2 bb = *(const float2*)(bias + col);
            acc[mt][nt][0] += bb.x;
            acc[mt][nt][1] += bb.y;
            acc[mt][nt][2] += bb.x;
            acc[mt][nt][3] += bb.y;
        }

    if (DO_LN) {
        __syncthreads();  // mainloop smem reads done before red[] reuse
#pragma unroll
        for (int mt = 0; mt < 2; mt++) {
            float s0 = 0.f, q0 = 0.f, s1 = 0.f, q1 = 0.f;
#pragma unroll
            for (int nt = 0; nt < 8; nt++) {
                float a = acc[mt][nt][0], b = acc[mt][nt][1];
                float c = acc[mt][nt][2], d = acc[mt][nt][3];
                s0 += a + b; q0 += a * a + b * b;
                s1 += c + d; q1 += c * c + d * d;
            }
#pragma unroll
            for (int o = 1; o < 4; o <<= 1) {
                s0 += __shfl_xor_sync(0xFFFFFFFFu, s0, o);
                q0 += __shfl_xor_sync(0xFFFFFFFFu, q0, o);
                s1 += __shfl_xor_sync(0xFFFFFFFFu, s1, o);
                q1 += __shfl_xor_sync(0xFFFFFFFFu, q1, o);
            }
            if (tig == 0) {
                int r0 = mt * 16 + g, r1 = r0 + 8;
                red[((warpM * 32 + r0) * 4 + warpN) * 2 + 0] = s0;
                red[((warpM * 32 + r0) * 4 + warpN) * 2 + 1] = q0;
                red[((warpM * 32 + r1) * 4 + warpN) * 2 + 0] = s1;
                red[((warpM * 32 + r1) * 4 + warpN) * 2 + 1] = q1;
            }
        }
        __syncthreads();

#pragma unroll
        for (int mt = 0; mt < 2; mt++) {
            int rl0 = mt * 16 + g, rl1 = rl0 + 8;
            float S0 = 0.f, Q0 = 0.f, S1 = 0.f, Q1 = 0.f;
#pragma unroll
            for (int w = 0; w < 4; w++) {
                S0 += red[((warpM * 32 + rl0) * 4 + w) * 2 + 0];
                Q0 += red[((warpM * 32 + rl0) * 4 + w) * 2 + 1];
                S1 += red[((warpM * 32 + rl1) * 4 + w) * 2 + 0];
                Q1 += red[((warpM * 32 + rl1) * 4 + w) * 2 + 1];
            }
            float mu0 = S0 * (1.0f / D);
            float rs0 = rsqrtf(fmaxf(Q0 * (1.0f / D) - mu0 * mu0, 0.f) + 1e-5f);
            float mu1 = S1 * (1.0f / D);
            float rs1 = rsqrtf(fmaxf(Q1 * (1.0f / D) - mu1 * mu1, 0.f) + 1e-5f);

            int r0 = row0 + warpM * 32 + rl0;
            int r1 = row0 + warpM * 32 + rl1;
#pragma unroll
            for (int nt = 0; nt < 8; nt++) {
                int col = warpN * 64 + nt * 8 + 2 * tig;
                float2 gg = *(const float2*)(gamma + col);
                float2 bb = *(const float2*)(beta + col);
                if (r0 < M) {
                    float t0 = (acc[mt][nt][0] - mu0) * rs0 * gg.x + bb.x;
                    float t1 = (acc[mt][nt][1] - mu0) * rs0 * gg.y + bb.y;
                    // round to tf32: next GEMM consumes without cvt
                    float2 o = make_float2(f2tf_f(gelu_exact(t0)), f2tf_f(gelu_exact(t1)));
                    *(float2*)(C + (size_t)r0 * D + col) = o;
                }
                if (r1 < M) {
                    float t2 = (acc[mt][nt][2] - mu1) * rs1 * gg.x + bb.x;
                    float t3 = (acc[mt][nt][3] - mu1) * rs1 * gg.y + bb.y;
                    float2 o = make_float2(f2tf_f(gelu_exact(t2)), f2tf_f(gelu_exact(t3)));
                    *(float2*)(C + (size_t)r1 * D + col) = o;
                }
            }
        }
    } else {
#pragma unroll
        for (int mt = 0; mt < 2; mt++) {
            int r0 = row0 + warpM * 32 + mt * 16 + g;
            int r1 = r0 + 8;
#pragma unroll
            for (int nt = 0; nt < 8; nt++) {
                int col = warpN * 64 + nt * 8 + 2 * tig;
                if (r0 < M) {
                    float2 o = make_float2(acc[mt][nt][0], acc[mt][nt][1]);
                    *(float2*)(C + (size_t)r0 * D + col) = o;
                }
                if (r1 < M) {
                    float2 o = make_float2(acc[mt][nt][2], acc[mt][nt][3]);
                    *(float2*)(C + (size_t)r1 * D + col) = o;
                }
            }
        }
    }
}

// ---------------------------------------------------------------------------
extern "C" void kernel_launch(void* const* d_in, const int* in_sizes, int n_in,
                              void* d_out, int out_size) {
    const float* xin = (const float*)d_in[0];
    const int* srcI  = (const int*)d_in[1];
    const int* dstI  = (const int*)d_in[2];
    const float* ew  = (const float*)d_in[3];
    const float* W1  = (const float*)d_in[4];
    const float* b1  = (const float*)d_in[5];
    const float* g1  = (const float*)d_in[6];
    const float* be1 = (const float*)d_in[7];
    const float* W2  = (const float*)d_in[8];
    const float* b2  = (const float*)d_in[9];
    const float* g2  = (const float*)d_in[10];
    const float* be2 = (const float*)d_in[11];
    const float* Wp  = (const float*)d_in[12];
    const float* bp  = (const float*)d_in[13];

    int n  = in_sizes[0] / D;   // 50000
    int nE = in_sizes[1];       // 800000

    float *agg, *xb, *ewc, *wt;
    int *deg, *rowptr, *wptr, *esrc;
    cudaGetSymbolAddress((void**)&agg, g_agg);
    cudaGetSymbolAddress((void**)&xb, g_x);
    cudaGetSymbolAddress((void**)&wt, g_wt);
    cudaGetSymbolAddress((void**)&deg, g_deg);
    cudaGetSymbolAddress((void**)&rowptr, g_rowptr);
    cudaGetSymbolAddress((void**)&wptr, g_wptr);
    cudaGetSymbolAddress((void**)&esrc, g_esrc);
    cudaGetSymbolAddress((void**)&ewc, g_ew);

    cudaFuncSetAttribute(gemm_fused<true>, cudaFuncAttributeMaxDynamicSharedMemorySize,
                         GEMM_SMEM_BYTES);
    cudaFuncSetAttribute(gemm_fused<false>, cudaFuncAttributeMaxDynamicSharedMemorySize,
                         GEMM_SMEM_BYTES);

    int gmBlocks = (n + 63) / 64;
    int gaBlocks = (n + 7) / 8;
    int eBlocks = (nE + 255) / 256;

    // ----- One-shot prep: CSR build + weight rounding -----
    round_weights<<<(3 * 16384 + 255) / 256, 256>>>(W1, W2, Wp, wt);
    zero_int<<<(n + 255) / 256, 256>>>(deg, n);
    hist_deg<<<eBlocks, 256>>>(dstI, deg, nE);
    scan_deg<<<1, SCAN_T>>>(deg, rowptr, wptr, n);
    fill_csr<<<eBlocks, 256>>>(srcI, dstI, ew, wptr, esrc, ewc, nE);

    const float* W1t = wt;
    const float* W2t = wt + D * D;
    const float* Wpt = wt + 2 * D * D;

    // ----- Layer 1 -----
    gather_agg<<<gaBlocks, 256>>>(xin, rowptr, esrc, ewc, agg, n);
    gemm_fused<true><<<gmBlocks, 256, GEMM_SMEM_BYTES>>>(agg, W1t, b1, g1, be1, xb, n);

    // ----- Layer 2 -----
    gather_agg<<<gaBlocks, 256>>>(xb, rowptr, esrc, ewc, agg, n);
    gemm_fused<true><<<gmBlocks, 256, GEMM_SMEM_BYTES>>>(agg, W2t, b2, g2, be2, xb, n);

    // ----- Output projection -----
    gemm_fused<false><<<gmBlocks, 256, GEMM_SMEM_BYTES>>>(xb, Wpt, bp, nullptr, nullptr,
                                                          (float*)d_out, n);
}

// round 10
// speedup vs baseline: 3.1196x; 1.2070x over previous
#include <cuda_runtime.h>
#include <cstdint>
#include <math.h>

#define D 256
#define MAXN 50048   // 50000 rounded up to 128
#define MAXE 1048576 // >= 800000

// Scratch (allocation-free rule: __device__ globals)
__device__ float g_agg[(size_t)MAXN * D];
__device__ float g_x[(size_t)MAXN * D];
__device__ float g_wt[3 * D * D];   // tf32-rounded W1|W2|Wp
__device__ int   g_deg[MAXN + 1];
__device__ int   g_rowptr[MAXN + 1];
__device__ int   g_wptr[MAXN + 1];
__device__ int   g_esrc[MAXE];
__device__ float g_ew[MAXE];
__device__ int   g_bsum[256];
__device__ int   g_boff[256];

__device__ __forceinline__ unsigned f2tf(float f) {
    unsigned r;
    asm("cvt.rna.tf32.f32 %0, %1;" : "=r"(r) : "f"(f));
    return r;
}
__device__ __forceinline__ float f2tf_f(float f) { return __uint_as_float(f2tf(f)); }

// ---------------------------------------------------------------------------
// Round three weight matrices to tf32 once per launch (inputs concatenated)
// ---------------------------------------------------------------------------
__global__ void round_weights(const float* __restrict__ w1, const float* __restrict__ w2,
                              const float* __restrict__ wp, float* __restrict__ out) {
    int i = blockIdx.x * blockDim.x + threadIdx.x;  // 0 .. 3*65536/4-1 (float4)
    const float* src = (i < 16384) ? w1 : (i < 32768) ? w2 : wp;
    int j = i & 16383;
    float4 v = ((const float4*)src)[j];
    float4 o;
    o.x = f2tf_f(v.x); o.y = f2tf_f(v.y); o.z = f2tf_f(v.z); o.w = f2tf_f(v.w);
    ((float4*)out)[i] = o;
}

// ---------------------------------------------------------------------------
// CSR build: zero -> histogram -> 3-kernel scan -> fill
// ---------------------------------------------------------------------------
__global__ void zero_int(int* p, int n) {
    int i = blockIdx.x * blockDim.x + threadIdx.x;
    if (i < n) p[i] = 0;
}

__global__ void hist_deg(const int* __restrict__ dstI, int* __restrict__ deg, int nE) {
    int i = blockIdx.x * blockDim.x + threadIdx.x;
    if (i < nE) atomicAdd(&deg[dstI[i]], 1);
}

// per-block exclusive scan of deg -> rowptr (local), block totals -> bsum
__global__ __launch_bounds__(256) void scan_block(const int* __restrict__ deg,
                                                  int* __restrict__ rowptr,
                                                  int* __restrict__ bsum, int n) {
    __shared__ int wsum[8];
    int i = blockIdx.x * 256 + threadIdx.x;
    int lane = threadIdx.x & 31, w = threadIdx.x >> 5;
    int v = (i < n) ? deg[i] : 0;
    int s = v;
#pragma unroll
    for (int o = 1; o < 32; o <<= 1) {
        int t = __shfl_up_sync(0xFFFFFFFFu, s, o);
        if (lane >= o) s += t;
    }
    if (lane == 31) wsum[w] = s;
    __syncthreads();
    if (w == 0) {
        int ws = (lane < 8) ? wsum[lane] : 0;
#pragma unroll
        for (int o = 1; o < 8; o <<= 1) {
            int t = __shfl_up_sync(0xFFFFFFFFu, ws, o);
            if (lane >= o) ws += t;
        }
        if (lane < 8) wsum[lane] = ws;  // inclusive warp totals
    }
    __syncthreads();
    int base = (w > 0) ? wsum[w - 1] : 0;
    if (i < n) rowptr[i] = base + s - v;  // exclusive, block-local
    if (threadIdx.x == 255) bsum[blockIdx.x] = wsum[7];  // block total
}

// scan the <=256 block totals; write grand total to rowptr[n]
__global__ __launch_bounds__(256) void scan_tops(const int* __restrict__ bsum,
                                                 int* __restrict__ boff,
                                                 int* __restrict__ rowptr, int nb, int n) {
    __shared__ int wsum[8];
    int lane = threadIdx.x & 31, w = threadIdx.x >> 5;
    int v = (threadIdx.x < nb) ? bsum[threadIdx.x] : 0;
    int s = v;
#pragma unroll
    for (int o = 1; o < 32; o <<= 1) {
        int t = __shfl_up_sync(0xFFFFFFFFu, s, o);
        if (lane >= o) s += t;
    }
    if (lane == 31) wsum[w] = s;
    __syncthreads();
    if (w == 0) {
        int ws = (lane < 8) ? wsum[lane] : 0;
#pragma unroll
        for (int o = 1; o < 8; o <<= 1) {
            int t = __shfl_up_sync(0xFFFFFFFFu, ws, o);
            if (lane >= o) ws += t;
        }
        if (lane < 8) wsum[lane] = ws;
    }
    __syncthreads();
    int base = (w > 0) ? wsum[w - 1] : 0;
    if (threadIdx.x < nb) boff[threadIdx.x] = base + s - v;  // exclusive
    if (threadIdx.x == 255) rowptr[n] = wsum[7];             // grand total
}

__global__ void add_off(int* __restrict__ rowptr, int* __restrict__ wptr,
                        const int* __restrict__ boff, int n) {
    int i = blockIdx.x * 256 + threadIdx.x;
    if (i < n) {
        int v = rowptr[i] + boff[blockIdx.x];
        rowptr[i] = v;
        wptr[i] = v;
    }
}

__global__ void fill_csr(const int* __restrict__ srcI, const int* __restrict__ dstI,
                         const float* __restrict__ ew, int* __restrict__ wptr,
                         int* __restrict__ esrc, float* __restrict__ ewOut, int nE) {
    int i = blockIdx.x * blockDim.x + threadIdx.x;
    if (i < nE) {
        int pos = atomicAdd(&wptr[dstI[i]], 1);
        esrc[pos] = srcI[i];
        ewOut[pos] = ew[i];
    }
}

// ---------------------------------------------------------------------------
// Gather: agg[i] = x[i] + sum_e w_e * x[src_e]. One warp per node, no atomics.
// Output rounded to tf32 (GEMM consumes it without in-loop cvt).
// ---------------------------------------------------------------------------
__device__ __forceinline__ void fma4(float4& a, float w, const float4& v) {
    a.x = fmaf(w, v.x, a.x);
    a.y = fmaf(w, v.y, a.y);
    a.z = fmaf(w, v.z, a.z);
    a.w = fmaf(w, v.w, a.w);
}

__global__ __launch_bounds__(256) void gather_agg(const float* __restrict__ x,
                                                  const int* __restrict__ rowptr,
                                                  const int* __restrict__ esrc,
                                                  const float* __restrict__ ew,
                                                  float* __restrict__ agg, int n) {
    int warp = (blockIdx.x * blockDim.x + threadIdx.x) >> 5;
    if (warp >= n) return;
    int lane = threadIdx.x & 31;

    const float4* xr = (const float4*)(x + (size_t)warp * D);
    float4 a0 = xr[lane];
    float4 a1 = xr[lane + 32];

    int e = rowptr[warp];
    int end = rowptr[warp + 1];
    for (; e + 2 <= end; e += 2) {
        int s0 = esrc[e], s1 = esrc[e + 1];
        float w0 = ew[e], w1 = ew[e + 1];
        const float4* p0 = (const float4*)(x + (size_t)s0 * D);
        const float4* p1 = (const float4*)(x + (size_t)s1 * D);
        float4 v00 = p0[lane], v01 = p0[lane + 32];
        float4 v10 = p1[lane], v11 = p1[lane + 32];
        fma4(a0, w0, v00);
        fma4(a1, w0, v01);
        fma4(a0, w1, v10);
        fma4(a1, w1, v11);
    }
    if (e < end) {
        int s0 = esrc[e];
        float w0 = ew[e];
        const float4* p0 = (const float4*)(x + (size_t)s0 * D);
        fma4(a0, w0, p0[lane]);
        fma4(a1, w0, p0[lane + 32]);
    }

    a0.x = f2tf_f(a0.x); a0.y = f2tf_f(a0.y); a0.z = f2tf_f(a0.z); a0.w = f2tf_f(a0.w);
    a1.x = f2tf_f(a1.x); a1.y = f2tf_f(a1.y); a1.z = f2tf_f(a1.z); a1.w = f2tf_f(a1.w);

    float4* ar = (float4*)(agg + (size_t)warp * D);
    ar[lane] = a0;
    ar[lane + 32] = a1;
}

// ---------------------------------------------------------------------------
// Fused TF32 GEMM (+bias, optional LayerNorm+GELU epilogue)
// Inputs already tf32-rounded in gmem -> no cvt in mainloop.
// cp.async double-buffered, ONE __syncthreads per k-tile.
// BM=64, BN=256, BK=32; 8 warps as 2(M) x 4(N); m16n8k8 tf32 mma.
// ---------------------------------------------------------------------------
__device__ __forceinline__ void mma_tf32(float& d0, float& d1, float& d2, float& d3,
                                         unsigned a0, unsigned a1, unsigned a2, unsigned a3,
                                         unsigned b0, unsigned b1) {
    asm volatile(
        "mma.sync.aligned.m16n8k8.row.col.f32.tf32.tf32.f32 "
        "{%0,%1,%2,%3}, {%4,%5,%6,%7}, {%8,%9}, {%0,%1,%2,%3};"
        : "+f"(d0), "+f"(d1), "+f"(d2), "+f"(d3)
        : "r"(a0), "r"(a1), "r"(a2), "r"(a3), "r"(b0), "r"(b1));
}

__device__ __forceinline__ float gelu_exact(float t) {
    return 0.5f * t * (1.0f + erff(t * 0.70710678118654752f));
}

__device__ __forceinline__ void cp_async16(unsigned int s, const void* g) {
    asm volatile("cp.async.cg.shared.global [%0], [%1], 16;" :: "r"(s), "l"(g));
}
__device__ __forceinline__ void cp_commit() {
    asm volatile("cp.async.commit_group;");
}
template <int N>
__device__ __forceinline__ void cp_wait() {
    asm volatile("cp.async.wait_group %0;" :: "n"(N));
}

#define AS_STRIDE 36   // conflict-free A frag loads (bank = 4g + tig)
#define BS_STRIDE 264  // conflict-free B frag loads (bank = 8k' + g)
#define AS_FLOATS (64 * AS_STRIDE)   // 2304
#define BS_FLOATS (32 * BS_STRIDE)   // 8448
#define RED_FLOATS 512
#define GEMM_SMEM_BYTES ((2 * AS_FLOATS + 2 * BS_FLOATS + RED_FLOATS) * 4)  // 88064

template <bool DO_LN>
__global__ __launch_bounds__(256) void gemm_fused(const float* __restrict__ A,
                                                  const float* __restrict__ B,
                                                  const float* __restrict__ bias,
                                                  const float* __restrict__ gamma,
                                                  const float* __restrict__ beta,
                                                  float* __restrict__ C, int M) {
    extern __shared__ float smem[];
    float* Asm[2] = {smem, smem + AS_FLOATS};
    float* Bsm[2] = {smem + 2 * AS_FLOATS, smem + 2 * AS_FLOATS + BS_FLOATS};
    float* red = smem + 2 * AS_FLOATS + 2 * BS_FLOATS;

    int tid = threadIdx.x;
    int row0 = blockIdx.x * 64;

    int wid = tid >> 5;
    int lane = tid & 31;
    int warpM = wid & 1;   // 2 warps down M (32 rows each)
    int warpN = wid >> 1;  // 4 warps across N (64 cols each)
    int g = lane >> 2;     // 0..7
    int tig = lane & 3;    // 0..3

    // A gmem->smem: 64 rows x 32 k; thread copies 8 floats of one row (2x cp16)
    int aRow = tid >> 2;
    int aOff = (tid & 3) * 8;
    int aRowG = min(row0 + aRow, M - 1);  // clamp; invalid rows masked at store
    const float* Ag = A + (size_t)aRowG * D + aOff;
    unsigned int aS[2];
    aS[0] = (unsigned int)__cvta_generic_to_shared(Asm[0] + aRow * AS_STRIDE + aOff);
    aS[1] = (unsigned int)__cvta_generic_to_shared(Asm[1] + aRow * AS_STRIDE + aOff);

    // B gmem->smem: 32 k-rows x 256 cols; thread copies 8 rows x 4 floats
    int bCol = (tid & 63) * 4;
    int bK0 = tid >> 6;
    const float* Bg = B + (size_t)bK0 * D + bCol;
    unsigned int bS[2];
    bS[0] = (unsigned int)__cvta_generic_to_shared(Bsm[0] + bK0 * BS_STRIDE + bCol);
    bS[1] = (unsigned int)__cvta_generic_to_shared(Bsm[1] + bK0 * BS_STRIDE + bCol);

    float acc[2][8][4];
#pragma unroll
    for (int mt = 0; mt < 2; mt++)
#pragma unroll
        for (int nt = 0; nt < 8; nt++)
#pragma unroll
            for (int c = 0; c < 4; c++) acc[mt][nt][c] = 0.0f;

    // prologue: issue tile 0
    {
        cp_async16(aS[0], Ag);
        cp_async16(aS[0] + 16, Ag + 4);
#pragma unroll
        for (int r = 0; r < 8; r++)
            cp_async16(bS[0] + r * 4 * BS_STRIDE * 4, Bg + (size_t)(r * 4) * D);
        cp_commit();
    }

#pragma unroll
    for (int kt = 0; kt < 8; kt++) {
        cp_wait<0>();
        __syncthreads();  // proves: tile kt landed AND all warps done with tile kt-1

        if (kt + 1 < 8) {  // copy(kt+1) overlaps compute(kt)
            int k0 = (kt + 1) * 32;
            int b = (kt + 1) & 1;
            cp_async16(aS[b], Ag + k0);
            cp_async16(aS[b] + 16, Ag + k0 + 4);
#pragma unroll
            for (int r = 0; r < 8; r++)
                cp_async16(bS[b] + r * 4 * BS_STRIDE * 4, Bg + (size_t)(k0 + r * 4) * D);
            cp_commit();
        }

        const float* Ab = Asm[kt & 1];
        const float* Bb = Bsm[kt & 1];
#pragma unroll
        for (int ks = 0; ks < 4; ks++) {
            int kk = ks * 8;
            unsigned af[2][4];
#pragma unroll
            for (int mt = 0; mt < 2; mt++) {
                int r = warpM * 32 + mt * 16 + g;
                const float* ap = &Ab[r * AS_STRIDE + kk];
                af[mt][0] = __float_as_uint(ap[tig]);
                af[mt][1] = __float_as_uint(ap[8 * AS_STRIDE + tig]);
                af[mt][2] = __float_as_uint(ap[tig + 4]);
                af[mt][3] = __float_as_uint(ap[8 * AS_STRIDE + tig + 4]);
            }
            unsigned bf[8][2];
#pragma unroll
            for (int nt = 0; nt < 8; nt++) {
                int c = warpN * 64 + nt * 8 + g;
                bf[nt][0] = __float_as_uint(Bb[(kk + tig) * BS_STRIDE + c]);
                bf[nt][1] = __float_as_uint(Bb[(kk + tig + 4) * BS_STRIDE + c]);
            }
#pragma unroll
            for (int mt = 0; mt < 2; mt++)
#pragma unroll
                for (int nt = 0; nt < 8; nt++)
                    mma_tf32(acc[mt][nt][0], acc[mt][nt][1], acc[mt][nt][2], acc[mt][nt][3],
                             af[mt][0], af[mt][1], af[mt][2], af[mt][3],
                             bf[nt][0], bf[nt][1]);
        }
    }

    // ---- bias add ----
#pragma unroll
    for (int mt = 0; mt < 2; mt++)
#pragma unroll
        for (int nt = 0; nt < 8; nt++) {
            int col = warpN * 64 + nt * 8 + 2 * tig;
            float2 bb = *(const float2*)(bias + col);
            acc[mt][nt][0] += bb.x;
            acc[mt][nt][1] += bb.y;
            acc[mt][nt][2] += bb.x;
            acc[mt][nt][3] += bb.y;
        }

    if (DO_LN) {
        __syncthreads();  // mainloop smem reads done before red[] reuse
#pragma unroll
        for (int mt = 0; mt < 2; mt++) {
            float s0 = 0.f, q0 = 0.f, s1 = 0.f, q1 = 0.f;
#pragma unroll
            for (int nt = 0; nt < 8; nt++) {
                float a = acc[mt][nt][0], b = acc[mt][nt][1];
                float c = acc[mt][nt][2], d = acc[mt][nt][3];
                s0 += a + b; q0 += a * a + b * b;
                s1 += c + d; q1 += c * c + d * d;
            }
#pragma unroll
            for (int o = 1; o < 4; o <<= 1) {
                s0 += __shfl_xor_sync(0xFFFFFFFFu, s0, o);
                q0 += __shfl_xor_sync(0xFFFFFFFFu, q0, o);
                s1 += __shfl_xor_sync(0xFFFFFFFFu, s1, o);
                q1 += __shfl_xor_sync(0xFFFFFFFFu, q1, o);
            }
            if (tig == 0) {
                int r0 = mt * 16 + g, r1 = r0 + 8;
                red[((warpM * 32 + r0) * 4 + warpN) * 2 + 0] = s0;
                red[((warpM * 32 + r0) * 4 + warpN) * 2 + 1] = q0;
                red[((warpM * 32 + r1) * 4 + warpN) * 2 + 0] = s1;
                red[((warpM * 32 + r1) * 4 + warpN) * 2 + 1] = q1;
            }
        }
        __syncthreads();

#pragma unroll
        for (int mt = 0; mt < 2; mt++) {
            int rl0 = mt * 16 + g, rl1 = rl0 + 8;
            float S0 = 0.f, Q0 = 0.f, S1 = 0.f, Q1 = 0.f;
#pragma unroll
            for (int w = 0; w < 4; w++) {
                S0 += red[((warpM * 32 + rl0) * 4 + w) * 2 + 0];
                Q0 += red[((warpM * 32 + rl0) * 4 + w) * 2 + 1];
                S1 += red[((warpM * 32 + rl1) * 4 + w) * 2 + 0];
                Q1 += red[((warpM * 32 + rl1) * 4 + w) * 2 + 1];
            }
            float mu0 = S0 * (1.0f / D);
            float rs0 = rsqrtf(fmaxf(Q0 * (1.0f / D) - mu0 * mu0, 0.f) + 1e-5f);
            float mu1 = S1 * (1.0f / D);
            float rs1 = rsqrtf(fmaxf(Q1 * (1.0f / D) - mu1 * mu1, 0.f) + 1e-5f);

            int r0 = row0 + warpM * 32 + rl0;
            int r1 = row0 + warpM * 32 + rl1;
#pragma unroll
            for (int nt = 0; nt < 8; nt++) {
                int col = warpN * 64 + nt * 8 + 2 * tig;
                float2 gg = *(const float2*)(gamma + col);
                float2 bb = *(const float2*)(beta + col);
                if (r0 < M) {
                    float t0 = (acc[mt][nt][0] - mu0) * rs0 * gg.x + bb.x;
                    float t1 = (acc[mt][nt][1] - mu0) * rs0 * gg.y + bb.y;
                    float2 o = make_float2(f2tf_f(gelu_exact(t0)), f2tf_f(gelu_exact(t1)));
                    *(float2*)(C + (size_t)r0 * D + col) = o;
                }
                if (r1 < M) {
                    float t2 = (acc[mt][nt][2] - mu1) * rs1 * gg.x + bb.x;
                    float t3 = (acc[mt][nt][3] - mu1) * rs1 * gg.y + bb.y;
                    float2 o = make_float2(f2tf_f(gelu_exact(t2)), f2tf_f(gelu_exact(t3)));
                    *(float2*)(C + (size_t)r1 * D + col) = o;
                }
            }
        }
    } else {
#pragma unroll
        for (int mt = 0; mt < 2; mt++) {
            int r0 = row0 + warpM * 32 + mt * 16 + g;
            int r1 = r0 + 8;
#pragma unroll
            for (int nt = 0; nt < 8; nt++) {
                int col = warpN * 64 + nt * 8 + 2 * tig;
                if (r0 < M) {
                    float2 o = make_float2(acc[mt][nt][0], acc[mt][nt][1]);
                    *(float2*)(C + (size_t)r0 * D + col) = o;
                }
                if (r1 < M) {
                    float2 o = make_float2(acc[mt][nt][2], acc[mt][nt][3]);
                    *(float2*)(C + (size_t)r1 * D + col) = o;
                }
            }
        }
    }
}

// ---------------------------------------------------------------------------
extern "C" void kernel_launch(void* const* d_in, const int* in_sizes, int n_in,
                              void* d_out, int out_size) {
    const float* xin = (const float*)d_in[0];
    const int* srcI  = (const int*)d_in[1];
    const int* dstI  = (const int*)d_in[2];
    const float* ew  = (const float*)d_in[3];
    const float* W1  = (const float*)d_in[4];
    const float* b1  = (const float*)d_in[5];
    const float* g1  = (const float*)d_in[6];
    const float* be1 = (const float*)d_in[7];
    const float* W2  = (const float*)d_in[8];
    const float* b2  = (const float*)d_in[9];
    const float* g2  = (const float*)d_in[10];
    const float* be2 = (const float*)d_in[11];
    const float* Wp  = (const float*)d_in[12];
    const float* bp  = (const float*)d_in[13];

    int n  = in_sizes[0] / D;   // 50000
    int nE = in_sizes[1];       // 800000

    float *agg, *xb, *ewc, *wt;
    int *deg, *rowptr, *wptr, *esrc, *bsum, *boff;
    cudaGetSymbolAddress((void**)&agg, g_agg);
    cudaGetSymbolAddress((void**)&xb, g_x);
    cudaGetSymbolAddress((void**)&wt, g_wt);
    cudaGetSymbolAddress((void**)&deg, g_deg);
    cudaGetSymbolAddress((void**)&rowptr, g_rowptr);
    cudaGetSymbolAddress((void**)&wptr, g_wptr);
    cudaGetSymbolAddress((void**)&esrc, g_esrc);
    cudaGetSymbolAddress((void**)&ewc, g_ew);
    cudaGetSymbolAddress((void**)&bsum, g_bsum);
    cudaGetSymbolAddress((void**)&boff, g_boff);

    cudaFuncSetAttribute(gemm_fused<true>, cudaFuncAttributeMaxDynamicSharedMemorySize,
                         GEMM_SMEM_BYTES);
    cudaFuncSetAttribute(gemm_fused<false>, cudaFuncAttributeMaxDynamicSharedMemorySize,
                         GEMM_SMEM_BYTES);

    int gmBlocks = (n + 63) / 64;
    int gaBlocks = (n + 7) / 8;
    int eBlocks = (nE + 255) / 256;
    int nBlocks = (n + 255) / 256;  // 196 (<=256 required by scan_tops)

    // ----- One-shot prep: weight rounding + CSR build -----
    round_weights<<<(3 * 16384 + 255) / 256, 256>>>(W1, W2, Wp, wt);
    zero_int<<<nBlocks, 256>>>(deg, n);
    hist_deg<<<eBlocks, 256>>>(dstI, deg, nE);
    scan_block<<<nBlocks, 256>>>(deg, rowptr, bsum, n);
    scan_tops<<<1, 256>>>(bsum, boff, rowptr, nBlocks, n);
    add_off<<<nBlocks, 256>>>(rowptr, wptr, boff, n);
    fill_csr<<<eBlocks, 256>>>(srcI, dstI, ew, wptr, esrc, ewc, nE);

    const float* W1t = wt;
    const float* W2t = wt + D * D;
    const float* Wpt = wt + 2 * D * D;

    // ----- Layer 1 -----
    gather_agg<<<gaBlocks, 256>>>(xin, rowptr, esrc, ewc, agg, n);
    gemm_fused<true><<<gmBlocks, 256, GEMM_SMEM_BYTES>>>(agg, W1t, b1, g1, be1, xb, n);

    // ----- Layer 2 -----
    gather_agg<<<gaBlocks, 256>>>(xb, rowptr, esrc, ewc, agg, n);
    gemm_fused<true><<<gmBlocks, 256, GEMM_SMEM_BYTES>>>(agg, W2t, b2, g2, be2, xb, n);

    // ----- Output projection -----
    gemm_fused<false><<<gmBlocks, 256, GEMM_SMEM_BYTES>>>(xb, Wpt, bp, nullptr, nullptr,
                                                          (float*)d_out, n);
}